// round 1
// baseline (speedup 1.0000x reference)
#include <cuda_runtime.h>
#include <math.h>
#include <stdint.h>

#define D_MODEL   512
#define D_FF      2048
#define N_EXPERTS 8
#define CAPACITY  10240
#define T_TOKENS  65536
#define NB        64          // blocks for count/rank (1024 tokens each)

#define OUT_ELEMS   ((long long)T_TOKENS * D_MODEL)      // 33554432
#define ONEHOT_E    ((long long)T_TOKENS * N_EXPERTS)    // 524288
#define PROBS_E     ((long long)T_TOKENS * N_EXPERTS)    // 524288

// ---------------- scratch (device globals; no allocations) ----------------
__device__ float g_probs[T_TOKENS * N_EXPERTS];
__device__ float g_top1[T_TOKENS];
__device__ int   g_expert[T_TOKENS];
__device__ int   g_pos[T_TOKENS];
__device__ int   g_blockCounts[NB * N_EXPERTS];
__device__ int   g_blockOffsets[NB * N_EXPERTS];
__device__ int   g_total[N_EXPERTS];
__device__ float g_pi_sum[N_EXPERTS];
__device__ float g_aux;
__device__ int   g_dropped;
__device__ int   g_slot2tok[N_EXPERTS * CAPACITY];
__device__ float g_H[(size_t)N_EXPERTS * CAPACITY * D_FF];   // 671 MB hidden scratch

// ---------------- kernels ----------------

__global__ void zero_kernel() {
    int i = threadIdx.x;
    if (i < N_EXPERTS) g_pi_sum[i] = 0.f;
}

// One warp per token. 8 tokens / block of 256 threads.
__global__ void router_kernel(const float* __restrict__ x,
                              const float* __restrict__ Wr,
                              const float* __restrict__ br) {
    __shared__ float Ws[N_EXPERTS * D_MODEL];
    __shared__ float brs[N_EXPERTS];
    __shared__ float pis[N_EXPERTS];
    int tid = threadIdx.x;
    for (int i = tid; i < N_EXPERTS * D_MODEL; i += 256) Ws[i] = Wr[i];
    if (tid < N_EXPERTS) { brs[tid] = br[tid]; pis[tid] = 0.f; }
    __syncthreads();

    int warp = tid >> 5, lane = tid & 31;
    int t = blockIdx.x * 8 + warp;

    float acc[N_EXPERTS];
#pragma unroll
    for (int e = 0; e < N_EXPERTS; e++) acc[e] = 0.f;

    const float* xr = x + (size_t)t * D_MODEL;
#pragma unroll
    for (int i = 0; i < D_MODEL / 32; i++) {
        int c = lane + i * 32;
        float v = xr[c];
#pragma unroll
        for (int e = 0; e < N_EXPERTS; e++) acc[e] += v * Ws[e * D_MODEL + c];
    }
#pragma unroll
    for (int e = 0; e < N_EXPERTS; e++) {
#pragma unroll
        for (int off = 16; off > 0; off >>= 1)
            acc[e] += __shfl_down_sync(0xffffffffu, acc[e], off);
    }

    if (lane == 0) {
        float l[N_EXPERTS];
        float mx = -INFINITY; int idx = 0;
#pragma unroll
        for (int e = 0; e < N_EXPERTS; e++) {
            l[e] = acc[e] + brs[e];
            if (l[e] > mx) { mx = l[e]; idx = e; }
        }
        float s = 0.f, pr[N_EXPERTS];
#pragma unroll
        for (int e = 0; e < N_EXPERTS; e++) { pr[e] = expf(l[e] - mx); s += pr[e]; }
        float inv = 1.f / s;
#pragma unroll
        for (int e = 0; e < N_EXPERTS; e++) {
            float p = pr[e] * inv;
            g_probs[(size_t)t * N_EXPERTS + e] = p;
            atomicAdd(&pis[e], p);
        }
        g_top1[t] = pr[idx] * inv;
        g_expert[t] = idx;
    }
    __syncthreads();
    if (tid < N_EXPERTS) atomicAdd(&g_pi_sum[tid], pis[tid]);
}

__global__ void count_kernel() {
    __shared__ int c[N_EXPERTS];
    if (threadIdx.x < N_EXPERTS) c[threadIdx.x] = 0;
    __syncthreads();
    int t = blockIdx.x * 1024 + threadIdx.x;
    atomicAdd(&c[g_expert[t]], 1);
    __syncthreads();
    if (threadIdx.x < N_EXPERTS)
        g_blockCounts[blockIdx.x * N_EXPERTS + threadIdx.x] = c[threadIdx.x];
}

__global__ void scan_kernel() {
    int e = threadIdx.x;
    if (e < N_EXPERTS) {
        int run = 0;
        for (int b = 0; b < NB; b++) {
            g_blockOffsets[b * N_EXPERTS + e] = run;
            run += g_blockCounts[b * N_EXPERTS + e];
        }
        g_total[e] = run;
    }
    __syncthreads();
    if (e == 0) {
        float aux = 0.f; int drop = 0;
        for (int k = 0; k < N_EXPERTS; k++) {
            int tot = g_total[k];
            int kept = tot < CAPACITY ? tot : CAPACITY;
            drop += tot - kept;
            float fi = (float)kept / (float)T_TOKENS;
            float pi = g_pi_sum[k] / (float)T_TOKENS;
            aux += fi * pi;
        }
        g_aux = aux * (float)N_EXPERTS;
        g_dropped = drop;
    }
}

__global__ void rank_kernel() {
    __shared__ int warpCnt[32][N_EXPERTS];
    __shared__ int warpOff[32][N_EXPERTS];
    int tid = threadIdx.x, w = tid >> 5, lane = tid & 31;
    int t = blockIdx.x * 1024 + tid;
    int e = g_expert[t];
    unsigned lt = (lane == 0) ? 0u : (0xffffffffu >> (32 - lane));
    int myrank = 0;
#pragma unroll
    for (int k = 0; k < N_EXPERTS; k++) {
        unsigned m = __ballot_sync(0xffffffffu, e == k);
        if (lane == 0) warpCnt[w][k] = __popc(m);
        if (e == k) myrank = __popc(m & lt);
    }
    __syncthreads();
    if (tid < 32 * N_EXPERTS) {
        int ww = tid >> 3, k = tid & 7;
        int s = 0;
        for (int u = 0; u < ww; u++) s += warpCnt[u][k];
        warpOff[ww][k] = s;
    }
    __syncthreads();
    int pos = g_blockOffsets[blockIdx.x * N_EXPERTS + e] + warpOff[w][e] + myrank;
    g_pos[t] = pos;
    if (pos < CAPACITY) g_slot2tok[e * CAPACITY + pos] = t;
}

// -------- GEMM1: H[e,m,:] = relu(X[tok(m),:] @ Wi[e]^T), 128x128x8 tiles --------
__global__ __launch_bounds__(256, 2)
void ffn1_kernel(const float* __restrict__ x, const float* __restrict__ Wi) {
    int e = blockIdx.z;
    int ne = g_total[e]; if (ne > CAPACITY) ne = CAPACITY;
    int m0 = blockIdx.y * 128;
    if (m0 >= ne) return;
    int n0 = blockIdx.x * 128;

    __shared__ float As[2][8][132];
    __shared__ float Bs[2][8][132];

    int tid = threadIdx.x;
    int lr = tid >> 1;            // 0..127
    int lk = (tid & 1) * 4;       // 0 or 4

    int slot_m = m0 + lr;
    int tok = (slot_m < ne) ? g_slot2tok[e * CAPACITY + slot_m] : 0;
    const float* arow = x + (size_t)tok * D_MODEL + lk;
    const float* brow = Wi + ((size_t)e * D_FF + (n0 + lr)) * D_MODEL + lk;

    float4 a = *(const float4*)arow;
    float4 b = *(const float4*)brow;
    As[0][lk + 0][lr] = a.x; As[0][lk + 1][lr] = a.y; As[0][lk + 2][lr] = a.z; As[0][lk + 3][lr] = a.w;
    Bs[0][lk + 0][lr] = b.x; Bs[0][lk + 1][lr] = b.y; Bs[0][lk + 2][lr] = b.z; Bs[0][lk + 3][lr] = b.w;
    __syncthreads();

    float acc[8][8];
#pragma unroll
    for (int i = 0; i < 8; i++)
#pragma unroll
        for (int j = 0; j < 8; j++) acc[i][j] = 0.f;

    int tx = tid & 15, ty = tid >> 4;
    const int KCH = D_MODEL / 8;

#pragma unroll 1
    for (int kc = 0; kc < KCH; kc++) {
        int cur = kc & 1;
        float4 na, nb;
        bool has = (kc + 1 < KCH);
        if (has) {
            na = *(const float4*)(arow + (kc + 1) * 8);
            nb = *(const float4*)(brow + (kc + 1) * 8);
        }
#pragma unroll
        for (int kk = 0; kk < 8; kk++) {
            float av[8], bv[8];
#pragma unroll
            for (int i = 0; i < 8; i++) av[i] = As[cur][kk][ty * 8 + i];
#pragma unroll
            for (int j = 0; j < 8; j++) bv[j] = Bs[cur][kk][tx * 8 + j];
#pragma unroll
            for (int i = 0; i < 8; i++)
#pragma unroll
                for (int j = 0; j < 8; j++) acc[i][j] += av[i] * bv[j];
        }
        if (has) {
            int nx = cur ^ 1;
            As[nx][lk + 0][lr] = na.x; As[nx][lk + 1][lr] = na.y; As[nx][lk + 2][lr] = na.z; As[nx][lk + 3][lr] = na.w;
            Bs[nx][lk + 0][lr] = nb.x; Bs[nx][lk + 1][lr] = nb.y; Bs[nx][lk + 2][lr] = nb.z; Bs[nx][lk + 3][lr] = nb.w;
            __syncthreads();
        }
    }

#pragma unroll
    for (int i = 0; i < 8; i++) {
        int m = m0 + ty * 8 + i;
        if (m < ne) {
            float* hp = g_H + ((size_t)e * CAPACITY + m) * D_FF + n0 + tx * 8;
#pragma unroll
            for (int j = 0; j < 8; j++) {
                float v = acc[i][j];
                hp[j] = v > 0.f ? v : 0.f;
            }
        }
    }
}

// -------- GEMM2: out[tok(m),:] = top1[tok] * (H[e,m,:] @ Wo[e]^T) --------
__global__ __launch_bounds__(256, 2)
void ffn2_kernel(const float* __restrict__ Wo, float* __restrict__ outp) {
    int e = blockIdx.z;
    int ne = g_total[e]; if (ne > CAPACITY) ne = CAPACITY;
    int m0 = blockIdx.y * 128;
    if (m0 >= ne) return;
    int n0 = blockIdx.x * 128;

    __shared__ float As[2][8][132];
    __shared__ float Bs[2][8][132];

    int tid = threadIdx.x;
    int lr = tid >> 1;
    int lk = (tid & 1) * 4;

    const float* arow = g_H + ((size_t)e * CAPACITY + (m0 + lr)) * D_FF + lk;
    const float* brow = Wo + ((size_t)e * D_MODEL + (n0 + lr)) * D_FF + lk;

    float4 a = *(const float4*)arow;
    float4 b = *(const float4*)brow;
    As[0][lk + 0][lr] = a.x; As[0][lk + 1][lr] = a.y; As[0][lk + 2][lr] = a.z; As[0][lk + 3][lr] = a.w;
    Bs[0][lk + 0][lr] = b.x; Bs[0][lk + 1][lr] = b.y; Bs[0][lk + 2][lr] = b.z; Bs[0][lk + 3][lr] = b.w;
    __syncthreads();

    float acc[8][8];
#pragma unroll
    for (int i = 0; i < 8; i++)
#pragma unroll
        for (int j = 0; j < 8; j++) acc[i][j] = 0.f;

    int tx = tid & 15, ty = tid >> 4;
    const int KCH = D_FF / 8;

#pragma unroll 1
    for (int kc = 0; kc < KCH; kc++) {
        int cur = kc & 1;
        float4 na, nb;
        bool has = (kc + 1 < KCH);
        if (has) {
            na = *(const float4*)(arow + (kc + 1) * 8);
            nb = *(const float4*)(brow + (kc + 1) * 8);
        }
#pragma unroll
        for (int kk = 0; kk < 8; kk++) {
            float av[8], bv[8];
#pragma unroll
            for (int i = 0; i < 8; i++) av[i] = As[cur][kk][ty * 8 + i];
#pragma unroll
            for (int j = 0; j < 8; j++) bv[j] = Bs[cur][kk][tx * 8 + j];
#pragma unroll
            for (int i = 0; i < 8; i++)
#pragma unroll
                for (int j = 0; j < 8; j++) acc[i][j] += av[i] * bv[j];
        }
        if (has) {
            int nx = cur ^ 1;
            As[nx][lk + 0][lr] = na.x; As[nx][lk + 1][lr] = na.y; As[nx][lk + 2][lr] = na.z; As[nx][lk + 3][lr] = na.w;
            Bs[nx][lk + 0][lr] = nb.x; Bs[nx][lk + 1][lr] = nb.y; Bs[nx][lk + 2][lr] = nb.z; Bs[nx][lk + 3][lr] = nb.w;
            __syncthreads();
        }
    }

#pragma unroll
    for (int i = 0; i < 8; i++) {
        int m = m0 + ty * 8 + i;
        if (m < ne) {
            int tok = g_slot2tok[e * CAPACITY + m];
            float scale = g_top1[tok];
            float* op = outp + (size_t)tok * D_MODEL + n0 + tx * 8;
#pragma unroll
            for (int j = 0; j < 8; j++) op[j] = acc[i][j] * scale;
        }
    }
}

__global__ void drop_kernel(float* __restrict__ outp) {
    for (int t = blockIdx.x * blockDim.x + threadIdx.x; t < T_TOKENS;
         t += gridDim.x * blockDim.x) {
        if (g_pos[t] >= CAPACITY) {
            float4 z = make_float4(0.f, 0.f, 0.f, 0.f);
            float4* p = (float4*)(outp + (size_t)t * D_MODEL);
            for (int i = 0; i < D_MODEL / 4; i++) p[i] = z;
        }
    }
}

// Fills the tail of d_out (if present) with onehot, top1, probs, aux, dropped.
__global__ void extras_kernel(float* __restrict__ outp, long long out_size) {
    long long i = (long long)blockIdx.x * blockDim.x + threadIdx.x;
    long long off = OUT_ELEMS + i;
    if (off >= out_size) return;
    long long r = i;
    if (r < ONEHOT_E) {
        int t = (int)(r >> 3), e = (int)(r & 7);
        outp[off] = (g_expert[t] == e && g_pos[t] < CAPACITY) ? 1.f : 0.f;
        return;
    }
    r -= ONEHOT_E;
    if (r < T_TOKENS) { outp[off] = g_top1[r]; return; }
    r -= T_TOKENS;
    if (r < PROBS_E) { outp[off] = g_probs[r]; return; }
    r -= PROBS_E;
    if (r == 0) { outp[off] = g_aux; return; }
    outp[off] = (float)g_dropped;
}

// ---------------- launch ----------------
extern "C" void kernel_launch(void* const* d_in, const int* in_sizes, int n_in,
                              void* d_out, int out_size) {
    const float* x  = (const float*)d_in[0];
    const float* Wr = (const float*)d_in[1];
    const float* br = (const float*)d_in[2];
    const float* Wi = (const float*)d_in[3];
    const float* Wo = (const float*)d_in[4];
    float* outp = (float*)d_out;

    zero_kernel<<<1, 32>>>();
    router_kernel<<<T_TOKENS / 8, 256>>>(x, Wr, br);
    count_kernel<<<NB, 1024>>>();
    scan_kernel<<<1, 32>>>();
    rank_kernel<<<NB, 1024>>>();

    dim3 g1(D_FF / 128, CAPACITY / 128, N_EXPERTS);
    ffn1_kernel<<<g1, 256>>>(x, Wi);
    dim3 g2(D_MODEL / 128, CAPACITY / 128, N_EXPERTS);
    ffn2_kernel<<<g2, 256>>>(Wo, outp);

    drop_kernel<<<256, 256>>>(outp);

    long long extra = (long long)out_size - OUT_ELEMS;
    if (extra > 0) {
        unsigned nb = (unsigned)((extra + 255) / 256);
        extras_kernel<<<nb, 256>>>(outp, (long long)out_size);
    }
}

// round 2
// speedup vs baseline: 1.0024x; 1.0024x over previous
#include <cuda_runtime.h>
#include <math.h>
#include <stdint.h>

#define D_MODEL   512
#define D_FF      2048
#define N_EXPERTS 8
#define CAPACITY  10240
#define T_TOKENS  65536
#define NB        64          // blocks for count/rank (1024 tokens each)

#define OUT_ELEMS   ((long long)T_TOKENS * D_MODEL)      // 33554432
#define ONEHOT_E    ((long long)T_TOKENS * N_EXPERTS)    // 524288
#define PROBS_E     ((long long)T_TOKENS * N_EXPERTS)    // 524288

// ---------------- scratch (device globals; no allocations) ----------------
__device__ float g_probs[T_TOKENS * N_EXPERTS];
__device__ float g_top1[T_TOKENS];
__device__ int   g_expert[T_TOKENS];
__device__ int   g_pos[T_TOKENS];
__device__ int   g_blockCounts[NB * N_EXPERTS];
__device__ int   g_blockOffsets[NB * N_EXPERTS];
__device__ int   g_total[N_EXPERTS];
__device__ float g_pi_sum[N_EXPERTS];
__device__ float g_aux;
__device__ int   g_dropped;
__device__ int   g_slot2tok[N_EXPERTS * CAPACITY];
__device__ float g_H[(size_t)N_EXPERTS * CAPACITY * D_FF];   // 671 MB hidden scratch

// ---------------- kernels ----------------

__global__ void zero_kernel() {
    int i = threadIdx.x;
    if (i < N_EXPERTS) g_pi_sum[i] = 0.f;
}

// One warp per token. 8 tokens / block of 256 threads.
__global__ void router_kernel(const float* __restrict__ x,
                              const float* __restrict__ Wr,
                              const float* __restrict__ br) {
    __shared__ float Ws[N_EXPERTS * D_MODEL];
    __shared__ float brs[N_EXPERTS];
    __shared__ float pis[N_EXPERTS];
    int tid = threadIdx.x;
    for (int i = tid; i < N_EXPERTS * D_MODEL; i += 256) Ws[i] = Wr[i];
    if (tid < N_EXPERTS) { brs[tid] = br[tid]; pis[tid] = 0.f; }
    __syncthreads();

    int warp = tid >> 5, lane = tid & 31;
    int t = blockIdx.x * 8 + warp;

    float acc[N_EXPERTS];
#pragma unroll
    for (int e = 0; e < N_EXPERTS; e++) acc[e] = 0.f;

    const float* xr = x + (size_t)t * D_MODEL;
#pragma unroll
    for (int i = 0; i < D_MODEL / 32; i++) {
        int c = lane + i * 32;
        float v = xr[c];
#pragma unroll
        for (int e = 0; e < N_EXPERTS; e++) acc[e] += v * Ws[e * D_MODEL + c];
    }
#pragma unroll
    for (int e = 0; e < N_EXPERTS; e++) {
#pragma unroll
        for (int off = 16; off > 0; off >>= 1)
            acc[e] += __shfl_down_sync(0xffffffffu, acc[e], off);
    }

    if (lane == 0) {
        float l[N_EXPERTS];
        float mx = -INFINITY; int idx = 0;
#pragma unroll
        for (int e = 0; e < N_EXPERTS; e++) {
            l[e] = acc[e] + brs[e];
            if (l[e] > mx) { mx = l[e]; idx = e; }
        }
        float s = 0.f, pr[N_EXPERTS];
#pragma unroll
        for (int e = 0; e < N_EXPERTS; e++) { pr[e] = expf(l[e] - mx); s += pr[e]; }
        float inv = 1.f / s;
#pragma unroll
        for (int e = 0; e < N_EXPERTS; e++) {
            float p = pr[e] * inv;
            g_probs[(size_t)t * N_EXPERTS + e] = p;
            atomicAdd(&pis[e], p);
        }
        g_top1[t] = pr[idx] * inv;
        g_expert[t] = idx;
    }
    __syncthreads();
    if (tid < N_EXPERTS) atomicAdd(&g_pi_sum[tid], pis[tid]);
}

__global__ void count_kernel() {
    __shared__ int c[N_EXPERTS];
    if (threadIdx.x < N_EXPERTS) c[threadIdx.x] = 0;
    __syncthreads();
    int t = blockIdx.x * 1024 + threadIdx.x;
    atomicAdd(&c[g_expert[t]], 1);
    __syncthreads();
    if (threadIdx.x < N_EXPERTS)
        g_blockCounts[blockIdx.x * N_EXPERTS + threadIdx.x] = c[threadIdx.x];
}

__global__ void scan_kernel() {
    int e = threadIdx.x;
    if (e < N_EXPERTS) {
        int run = 0;
        for (int b = 0; b < NB; b++) {
            g_blockOffsets[b * N_EXPERTS + e] = run;
            run += g_blockCounts[b * N_EXPERTS + e];
        }
        g_total[e] = run;
    }
    __syncthreads();
    if (e == 0) {
        float aux = 0.f; int drop = 0;
        for (int k = 0; k < N_EXPERTS; k++) {
            int tot = g_total[k];
            int kept = tot < CAPACITY ? tot : CAPACITY;
            drop += tot - kept;
            float fi = (float)kept / (float)T_TOKENS;
            float pi = g_pi_sum[k] / (float)T_TOKENS;
            aux += fi * pi;
        }
        g_aux = aux * (float)N_EXPERTS;
        g_dropped = drop;
    }
}

__global__ void rank_kernel() {
    __shared__ int warpCnt[32][N_EXPERTS];
    __shared__ int warpOff[32][N_EXPERTS];
    int tid = threadIdx.x, w = tid >> 5, lane = tid & 31;
    int t = blockIdx.x * 1024 + tid;
    int e = g_expert[t];
    unsigned lt = (lane == 0) ? 0u : (0xffffffffu >> (32 - lane));
    int myrank = 0;
#pragma unroll
    for (int k = 0; k < N_EXPERTS; k++) {
        unsigned m = __ballot_sync(0xffffffffu, e == k);
        if (lane == 0) warpCnt[w][k] = __popc(m);
        if (e == k) myrank = __popc(m & lt);
    }
    __syncthreads();
    if (tid < 32 * N_EXPERTS) {
        int ww = tid >> 3, k = tid & 7;
        int s = 0;
        for (int u = 0; u < ww; u++) s += warpCnt[u][k];
        warpOff[ww][k] = s;
    }
    __syncthreads();
    int pos = g_blockOffsets[blockIdx.x * N_EXPERTS + e] + warpOff[w][e] + myrank;
    g_pos[t] = pos;
    if (pos < CAPACITY) g_slot2tok[e * CAPACITY + pos] = t;
}

// -------- GEMM1: H[e,m,:] = relu(X[tok(m),:] @ Wi[e]^T), 128x128x8 tiles --------
__global__ __launch_bounds__(256, 2)
void ffn1_kernel(const float* __restrict__ x, const float* __restrict__ Wi) {
    int e = blockIdx.z;
    int ne = g_total[e]; if (ne > CAPACITY) ne = CAPACITY;
    int m0 = blockIdx.y * 128;
    if (m0 >= ne) return;
    int n0 = blockIdx.x * 128;

    __shared__ float As[2][8][132];
    __shared__ float Bs[2][8][132];

    int tid = threadIdx.x;
    int lr = tid >> 1;            // 0..127
    int lk = (tid & 1) * 4;       // 0 or 4

    int slot_m = m0 + lr;
    int tok = (slot_m < ne) ? g_slot2tok[e * CAPACITY + slot_m] : 0;
    const float* arow = x + (size_t)tok * D_MODEL + lk;
    const float* brow = Wi + ((size_t)e * D_FF + (n0 + lr)) * D_MODEL + lk;

    float4 a = *(const float4*)arow;
    float4 b = *(const float4*)brow;
    As[0][lk + 0][lr] = a.x; As[0][lk + 1][lr] = a.y; As[0][lk + 2][lr] = a.z; As[0][lk + 3][lr] = a.w;
    Bs[0][lk + 0][lr] = b.x; Bs[0][lk + 1][lr] = b.y; Bs[0][lk + 2][lr] = b.z; Bs[0][lk + 3][lr] = b.w;
    __syncthreads();

    float acc[8][8];
#pragma unroll
    for (int i = 0; i < 8; i++)
#pragma unroll
        for (int j = 0; j < 8; j++) acc[i][j] = 0.f;

    int tx = tid & 15, ty = tid >> 4;
    const int KCH = D_MODEL / 8;

#pragma unroll 1
    for (int kc = 0; kc < KCH; kc++) {
        int cur = kc & 1;
        float4 na, nb;
        bool has = (kc + 1 < KCH);
        if (has) {
            na = *(const float4*)(arow + (kc + 1) * 8);
            nb = *(const float4*)(brow + (kc + 1) * 8);
        }
#pragma unroll
        for (int kk = 0; kk < 8; kk++) {
            float av[8], bv[8];
#pragma unroll
            for (int i = 0; i < 8; i++) av[i] = As[cur][kk][ty * 8 + i];
#pragma unroll
            for (int j = 0; j < 8; j++) bv[j] = Bs[cur][kk][tx * 8 + j];
#pragma unroll
            for (int i = 0; i < 8; i++)
#pragma unroll
                for (int j = 0; j < 8; j++) acc[i][j] += av[i] * bv[j];
        }
        if (has) {
            int nx = cur ^ 1;
            As[nx][lk + 0][lr] = na.x; As[nx][lk + 1][lr] = na.y; As[nx][lk + 2][lr] = na.z; As[nx][lk + 3][lr] = na.w;
            Bs[nx][lk + 0][lr] = nb.x; Bs[nx][lk + 1][lr] = nb.y; Bs[nx][lk + 2][lr] = nb.z; Bs[nx][lk + 3][lr] = nb.w;
            __syncthreads();
        }
    }

#pragma unroll
    for (int i = 0; i < 8; i++) {
        int m = m0 + ty * 8 + i;
        if (m < ne) {
            float* hp = g_H + ((size_t)e * CAPACITY + m) * D_FF + n0 + tx * 8;
#pragma unroll
            for (int j = 0; j < 8; j++) {
                float v = acc[i][j];
                hp[j] = v > 0.f ? v : 0.f;
            }
        }
    }
}

// -------- GEMM2: out[tok(m),:] = top1[tok] * (H[e,m,:] @ Wo[e]^T) --------
__global__ __launch_bounds__(256, 2)
void ffn2_kernel(const float* __restrict__ Wo, float* __restrict__ outp) {
    int e = blockIdx.z;
    int ne = g_total[e]; if (ne > CAPACITY) ne = CAPACITY;
    int m0 = blockIdx.y * 128;
    if (m0 >= ne) return;
    int n0 = blockIdx.x * 128;

    __shared__ float As[2][8][132];
    __shared__ float Bs[2][8][132];

    int tid = threadIdx.x;
    int lr = tid >> 1;
    int lk = (tid & 1) * 4;

    const float* arow = g_H + ((size_t)e * CAPACITY + (m0 + lr)) * D_FF + lk;
    const float* brow = Wo + ((size_t)e * D_MODEL + (n0 + lr)) * D_FF + lk;

    float4 a = *(const float4*)arow;
    float4 b = *(const float4*)brow;
    As[0][lk + 0][lr] = a.x; As[0][lk + 1][lr] = a.y; As[0][lk + 2][lr] = a.z; As[0][lk + 3][lr] = a.w;
    Bs[0][lk + 0][lr] = b.x; Bs[0][lk + 1][lr] = b.y; Bs[0][lk + 2][lr] = b.z; Bs[0][lk + 3][lr] = b.w;
    __syncthreads();

    float acc[8][8];
#pragma unroll
    for (int i = 0; i < 8; i++)
#pragma unroll
        for (int j = 0; j < 8; j++) acc[i][j] = 0.f;

    int tx = tid & 15, ty = tid >> 4;
    const int KCH = D_FF / 8;

#pragma unroll 1
    for (int kc = 0; kc < KCH; kc++) {
        int cur = kc & 1;
        float4 na, nb;
        bool has = (kc + 1 < KCH);
        if (has) {
            na = *(const float4*)(arow + (kc + 1) * 8);
            nb = *(const float4*)(brow + (kc + 1) * 8);
        }
#pragma unroll
        for (int kk = 0; kk < 8; kk++) {
            float av[8], bv[8];
#pragma unroll
            for (int i = 0; i < 8; i++) av[i] = As[cur][kk][ty * 8 + i];
#pragma unroll
            for (int j = 0; j < 8; j++) bv[j] = Bs[cur][kk][tx * 8 + j];
#pragma unroll
            for (int i = 0; i < 8; i++)
#pragma unroll
                for (int j = 0; j < 8; j++) acc[i][j] += av[i] * bv[j];
        }
        if (has) {
            int nx = cur ^ 1;
            As[nx][lk + 0][lr] = na.x; As[nx][lk + 1][lr] = na.y; As[nx][lk + 2][lr] = na.z; As[nx][lk + 3][lr] = na.w;
            Bs[nx][lk + 0][lr] = nb.x; Bs[nx][lk + 1][lr] = nb.y; Bs[nx][lk + 2][lr] = nb.z; Bs[nx][lk + 3][lr] = nb.w;
            __syncthreads();
        }
    }

#pragma unroll
    for (int i = 0; i < 8; i++) {
        int m = m0 + ty * 8 + i;
        if (m < ne) {
            int tok = g_slot2tok[e * CAPACITY + m];
            float scale = g_top1[tok];
            float* op = outp + (size_t)tok * D_MODEL + n0 + tx * 8;
#pragma unroll
            for (int j = 0; j < 8; j++) op[j] = acc[i][j] * scale;
        }
    }
}

__global__ void drop_kernel(float* __restrict__ outp) {
    for (int t = blockIdx.x * blockDim.x + threadIdx.x; t < T_TOKENS;
         t += gridDim.x * blockDim.x) {
        if (g_pos[t] >= CAPACITY) {
            float4 z = make_float4(0.f, 0.f, 0.f, 0.f);
            float4* p = (float4*)(outp + (size_t)t * D_MODEL);
            for (int i = 0; i < D_MODEL / 4; i++) p[i] = z;
        }
    }
}

// Fills the tail of d_out (if present) with onehot, top1, probs, aux, dropped.
__global__ void extras_kernel(float* __restrict__ outp, long long out_size) {
    long long i = (long long)blockIdx.x * blockDim.x + threadIdx.x;
    long long off = OUT_ELEMS + i;
    if (off >= out_size) return;
    long long r = i;
    if (r < ONEHOT_E) {
        int t = (int)(r >> 3), e = (int)(r & 7);
        outp[off] = (g_expert[t] == e && g_pos[t] < CAPACITY) ? 1.f : 0.f;
        return;
    }
    r -= ONEHOT_E;
    if (r < T_TOKENS) { outp[off] = g_top1[r]; return; }
    r -= T_TOKENS;
    if (r < PROBS_E) { outp[off] = g_probs[r]; return; }
    r -= PROBS_E;
    if (r == 0) { outp[off] = g_aux; return; }
    outp[off] = (float)g_dropped;
}

// ---------------- launch ----------------
extern "C" void kernel_launch(void* const* d_in, const int* in_sizes, int n_in,
                              void* d_out, int out_size) {
    const float* x  = (const float*)d_in[0];
    const float* Wr = (const float*)d_in[1];
    const float* br = (const float*)d_in[2];
    const float* Wi = (const float*)d_in[3];
    const float* Wo = (const float*)d_in[4];
    float* outp = (float*)d_out;

    zero_kernel<<<1, 32>>>();
    router_kernel<<<T_TOKENS / 8, 256>>>(x, Wr, br);
    count_kernel<<<NB, 1024>>>();
    scan_kernel<<<1, 32>>>();
    rank_kernel<<<NB, 1024>>>();

    dim3 g1(D_FF / 128, CAPACITY / 128, N_EXPERTS);
    ffn1_kernel<<<g1, 256>>>(x, Wi);
    dim3 g2(D_MODEL / 128, CAPACITY / 128, N_EXPERTS);
    ffn2_kernel<<<g2, 256>>>(Wo, outp);

    drop_kernel<<<256, 256>>>(outp);

    long long extra = (long long)out_size - OUT_ELEMS;
    if (extra > 0) {
        unsigned nb = (unsigned)((extra + 255) / 256);
        extras_kernel<<<nb, 256>>>(outp, (long long)out_size);
    }
}

// round 4
// speedup vs baseline: 2.0602x; 2.0553x over previous
#include <cuda_runtime.h>
#include <math.h>
#include <stdint.h>

#define D_MODEL   512
#define D_FF      2048
#define N_EXPERTS 8
#define CAPACITY  10240
#define T_TOKENS  65536
#define NB        64

#define OUT_ELEMS   ((long long)T_TOKENS * D_MODEL)
#define ONEHOT_E    ((long long)T_TOKENS * N_EXPERTS)
#define PROBS_E     ((long long)T_TOKENS * N_EXPERTS)

// ---------------- scratch ----------------
__device__ float g_probs[T_TOKENS * N_EXPERTS];
__device__ float g_top1[T_TOKENS];
__device__ int   g_expert[T_TOKENS];
__device__ int   g_pos[T_TOKENS];
__device__ int   g_blockCounts[NB * N_EXPERTS];
__device__ int   g_blockOffsets[NB * N_EXPERTS];
__device__ int   g_total[N_EXPERTS];
__device__ float g_pi_sum[N_EXPERTS];
__device__ float g_aux;
__device__ int   g_dropped;
__device__ int   g_slot2tok[N_EXPERTS * CAPACITY];
__device__ float g_H[(size_t)N_EXPERTS * CAPACITY * D_FF];

// ---------------- helpers ----------------
__device__ __forceinline__ uint32_t s2u(const void* p) {
    uint32_t a;
    asm("{ .reg .u64 t; cvta.to.shared.u64 t, %1; cvt.u32.u64 %0, t; }" : "=r"(a) : "l"(p));
    return a;
}
__device__ __forceinline__ void cpasync16(uint32_t saddr, const void* gaddr) {
    asm volatile("cp.async.cg.shared.global [%0], [%1], 16;" :: "r"(saddr), "l"(gaddr) : "memory");
}
__device__ __forceinline__ uint32_t f2tf(float x) {
    uint32_t u; asm("cvt.rna.tf32.f32 %0, %1;" : "=r"(u) : "f"(x));
    return u;
}
__device__ __forceinline__ float tf32r(float x) {
    uint32_t u; asm("cvt.rna.tf32.f32 %0, %1;" : "=r"(u) : "f"(x));
    return __uint_as_float(u);
}
__device__ __forceinline__ void mma8(float* c, const uint32_t* a, const uint32_t* b) {
    asm volatile(
        "mma.sync.aligned.m16n8k8.row.col.f32.tf32.tf32.f32 "
        "{%0,%1,%2,%3}, {%4,%5,%6,%7}, {%8,%9}, {%0,%1,%2,%3};"
        : "+f"(c[0]), "+f"(c[1]), "+f"(c[2]), "+f"(c[3])
        : "r"(a[0]), "r"(a[1]), "r"(a[2]), "r"(a[3]), "r"(b[0]), "r"(b[1]));
}

// ---------------- routing (known-correct from R1) ----------------
__global__ void zero_kernel() {
    int i = threadIdx.x;
    if (i < N_EXPERTS) g_pi_sum[i] = 0.f;
}

__global__ void router_kernel(const float* __restrict__ x,
                              const float* __restrict__ Wr,
                              const float* __restrict__ br) {
    __shared__ float Ws[N_EXPERTS * D_MODEL];
    __shared__ float brs[N_EXPERTS];
    __shared__ float pis[N_EXPERTS];
    int tid = threadIdx.x;
    for (int i = tid; i < N_EXPERTS * D_MODEL; i += 256) Ws[i] = Wr[i];
    if (tid < N_EXPERTS) { brs[tid] = br[tid]; pis[tid] = 0.f; }
    __syncthreads();

    int warp = tid >> 5, lane = tid & 31;
    int t = blockIdx.x * 8 + warp;

    float acc[N_EXPERTS];
#pragma unroll
    for (int e = 0; e < N_EXPERTS; e++) acc[e] = 0.f;
    const float* xr = x + (size_t)t * D_MODEL;
#pragma unroll
    for (int i = 0; i < D_MODEL / 32; i++) {
        int c = lane + i * 32;
        float v = xr[c];
#pragma unroll
        for (int e = 0; e < N_EXPERTS; e++) acc[e] += v * Ws[e * D_MODEL + c];
    }
#pragma unroll
    for (int e = 0; e < N_EXPERTS; e++) {
#pragma unroll
        for (int off = 16; off > 0; off >>= 1)
            acc[e] += __shfl_down_sync(0xffffffffu, acc[e], off);
    }
    if (lane == 0) {
        float l[N_EXPERTS];
        float mx = -INFINITY; int idx = 0;
#pragma unroll
        for (int e = 0; e < N_EXPERTS; e++) {
            l[e] = acc[e] + brs[e];
            if (l[e] > mx) { mx = l[e]; idx = e; }
        }
        float s = 0.f, pr[N_EXPERTS];
#pragma unroll
        for (int e = 0; e < N_EXPERTS; e++) { pr[e] = expf(l[e] - mx); s += pr[e]; }
        float inv = 1.f / s;
#pragma unroll
        for (int e = 0; e < N_EXPERTS; e++) {
            float p = pr[e] * inv;
            g_probs[(size_t)t * N_EXPERTS + e] = p;
            atomicAdd(&pis[e], p);
        }
        g_top1[t] = pr[idx] * inv;
        g_expert[t] = idx;
    }
    __syncthreads();
    if (tid < N_EXPERTS) atomicAdd(&g_pi_sum[tid], pis[tid]);
}

__global__ void count_kernel() {
    __shared__ int c[N_EXPERTS];
    if (threadIdx.x < N_EXPERTS) c[threadIdx.x] = 0;
    __syncthreads();
    int t = blockIdx.x * 1024 + threadIdx.x;
    atomicAdd(&c[g_expert[t]], 1);
    __syncthreads();
    if (threadIdx.x < N_EXPERTS)
        g_blockCounts[blockIdx.x * N_EXPERTS + threadIdx.x] = c[threadIdx.x];
}

__global__ void scan_kernel() {
    int e = threadIdx.x;
    if (e < N_EXPERTS) {
        int run = 0;
        for (int b = 0; b < NB; b++) {
            g_blockOffsets[b * N_EXPERTS + e] = run;
            run += g_blockCounts[b * N_EXPERTS + e];
        }
        g_total[e] = run;
    }
    __syncthreads();
    if (e == 0) {
        float aux = 0.f; int drop = 0;
        for (int k = 0; k < N_EXPERTS; k++) {
            int tot = g_total[k];
            int kept = tot < CAPACITY ? tot : CAPACITY;
            drop += tot - kept;
            float fi = (float)kept / (float)T_TOKENS;
            float pi = g_pi_sum[k] / (float)T_TOKENS;
            aux += fi * pi;
        }
        g_aux = aux * (float)N_EXPERTS;
        g_dropped = drop;
    }
}

__global__ void rank_kernel() {
    __shared__ int warpCnt[32][N_EXPERTS];
    __shared__ int warpOff[32][N_EXPERTS];
    int tid = threadIdx.x, w = tid >> 5, lane = tid & 31;
    int t = blockIdx.x * 1024 + tid;
    int e = g_expert[t];
    unsigned lt = (lane == 0) ? 0u : (0xffffffffu >> (32 - lane));
    int myrank = 0;
#pragma unroll
    for (int k = 0; k < N_EXPERTS; k++) {
        unsigned m = __ballot_sync(0xffffffffu, e == k);
        if (lane == 0) warpCnt[w][k] = __popc(m);
        if (e == k) myrank = __popc(m & lt);
    }
    __syncthreads();
    if (tid < 32 * N_EXPERTS) {
        int ww = tid >> 3, k = tid & 7;
        int s = 0;
        for (int u = 0; u < ww; u++) s += warpCnt[u][k];
        warpOff[ww][k] = s;
    }
    __syncthreads();
    int pos = g_blockOffsets[blockIdx.x * N_EXPERTS + e] + warpOff[w][e] + myrank;
    g_pos[t] = pos;
    if (pos < CAPACITY) g_slot2tok[e * CAPACITY + pos] = t;
}

// ---------------- tf32 mma.sync GEMM ----------------
// D[128,128] = A(rows) @ B(rows)^T over K_TOT.  512 threads, 4x4 warps,
// warp tile 32x32, BK=16 double-buffered via cp.async.
// GATHER: A rows = x[slot2tok]; else A rows = g_H slots.
// RELU:   D -> relu+tf32round -> g_H; else D -> *top1, scatter to out.
template<int K_TOT, bool GATHER, bool RELU>
__global__ void __launch_bounds__(512, 1)
gemm_mma(const float* __restrict__ Aglob, const float* __restrict__ Bglob,
         float* __restrict__ Dglob) {
    constexpr int BK = 16, LDS = 20;
    __shared__ float sA[2][128 * LDS];
    __shared__ float sB[2][128 * LDS];
    __shared__ int tokS[128];

    int e = blockIdx.z;
    int ne = g_total[e]; if (ne > CAPACITY) ne = CAPACITY;
    int m0 = blockIdx.y * 128;
    if (m0 >= ne) return;
    int n0 = blockIdx.x * 128;

    int tid = threadIdx.x;
    int wid = tid >> 5, lane = tid & 31;
    int wm = wid >> 2, wn = wid & 3;

    if (GATHER && tid < 128) {
        int m = m0 + tid;
        tokS[tid] = (m < ne) ? g_slot2tok[e * CAPACITY + m] : 0;
    }
    __syncthreads();

    const float* Bbase = Bglob + ((size_t)e * (RELU ? D_FF : D_MODEL) + n0) * K_TOT;
    const float* Hbase = g_H + ((size_t)e * CAPACITY + m0) * (size_t)D_FF;

    // loader: 512 threads, 1 float4 of A + 1 of B per stage
    int lrow = tid >> 2, lq = tid & 3;
    const float* aRowPtr;
    if (GATHER) aRowPtr = Aglob + (size_t)tokS[lrow] * D_MODEL + lq * 4;
    else        aRowPtr = Hbase + (size_t)lrow * D_FF + lq * 4;
    const float* bRowPtr = Bbase + (size_t)lrow * K_TOT + lq * 4;
    uint32_t sAu = s2u(&sA[0][0]) + (lrow * LDS + lq * 4) * 4;
    uint32_t sBu = s2u(&sB[0][0]) + (lrow * LDS + lq * 4) * 4;
    const uint32_t bufStride = 128 * LDS * 4;

    float acc[2][4][4];
#pragma unroll
    for (int mi = 0; mi < 2; mi++)
#pragma unroll
        for (int ni = 0; ni < 4; ni++)
#pragma unroll
            for (int r = 0; r < 4; r++) acc[mi][ni][r] = 0.f;

    // prologue
    cpasync16(sAu, aRowPtr);
    cpasync16(sBu, bRowPtr);
    asm volatile("cp.async.commit_group;" ::: "memory");

    const int NS = K_TOT / BK;
    for (int s = 0; s < NS; s++) {
        asm volatile("cp.async.wait_group 0;" ::: "memory");
        __syncthreads();
        if (s + 1 < NS) {
            int nb = (s + 1) & 1;
            cpasync16(sAu + nb * bufStride, aRowPtr + (s + 1) * BK);
            cpasync16(sBu + nb * bufStride, bRowPtr + (s + 1) * BK);
            asm volatile("cp.async.commit_group;" ::: "memory");
        }
        const float* A = sA[s & 1];
        const float* B = sB[s & 1];
#pragma unroll
        for (int kf = 0; kf < 2; kf++) {
            int kc = kf * 8 + (lane & 3);
            uint32_t a[2][4], b[4][2];
#pragma unroll
            for (int mi = 0; mi < 2; mi++) {
                int r = wm * 32 + mi * 16 + (lane >> 2);
                a[mi][0] = f2tf(A[r * LDS + kc]);
                a[mi][1] = f2tf(A[(r + 8) * LDS + kc]);
                a[mi][2] = f2tf(A[r * LDS + kc + 4]);
                a[mi][3] = f2tf(A[(r + 8) * LDS + kc + 4]);
            }
#pragma unroll
            for (int ni = 0; ni < 4; ni++) {
                int r = wn * 32 + ni * 8 + (lane >> 2);
                b[ni][0] = f2tf(B[r * LDS + kc]);
                b[ni][1] = f2tf(B[r * LDS + kc + 4]);
            }
#pragma unroll
            for (int mi = 0; mi < 2; mi++)
#pragma unroll
                for (int ni = 0; ni < 4; ni++)
                    mma8(acc[mi][ni], a[mi], b[ni]);
        }
    }

    // epilogue
#pragma unroll
    for (int mi = 0; mi < 2; mi++) {
#pragma unroll
        for (int half = 0; half < 2; half++) {
            int m = m0 + wm * 32 + mi * 16 + (lane >> 2) + half * 8;
            bool valid = m < ne;
            float sc = 1.f;
            float* rowptr;
            if (RELU) {
                rowptr = g_H + ((size_t)e * CAPACITY + m) * D_FF + n0;
            } else {
                int tk = valid ? g_slot2tok[e * CAPACITY + m] : 0;
                sc = g_top1[tk];
                rowptr = Dglob + (size_t)tk * D_MODEL + n0;
            }
            if (valid) {
#pragma unroll
                for (int ni = 0; ni < 4; ni++) {
                    int c = wn * 32 + ni * 8 + 2 * (lane & 3);
                    float v0 = acc[mi][ni][half * 2 + 0];
                    float v1 = acc[mi][ni][half * 2 + 1];
                    float2 v;
                    if (RELU) {
                        v.x = tf32r(fmaxf(v0, 0.f));
                        v.y = tf32r(fmaxf(v1, 0.f));
                    } else {
                        v.x = v0 * sc;
                        v.y = v1 * sc;
                    }
                    *(float2*)(rowptr + c) = v;
                }
            }
        }
    }
}

__global__ void drop_kernel(float* __restrict__ outp) {
    for (int t = blockIdx.x * blockDim.x + threadIdx.x; t < T_TOKENS;
         t += gridDim.x * blockDim.x) {
        if (g_pos[t] >= CAPACITY) {
            float4 z = make_float4(0.f, 0.f, 0.f, 0.f);
            float4* p = (float4*)(outp + (size_t)t * D_MODEL);
            for (int i = 0; i < D_MODEL / 4; i++) p[i] = z;
        }
    }
}

__global__ void extras_kernel(float* __restrict__ outp, long long out_size) {
    long long i = (long long)blockIdx.x * blockDim.x + threadIdx.x;
    long long off = OUT_ELEMS + i;
    if (off >= out_size) return;
    long long r = i;
    if (r < ONEHOT_E) {
        int t = (int)(r >> 3), e = (int)(r & 7);
        outp[off] = (g_expert[t] == e && g_pos[t] < CAPACITY) ? 1.f : 0.f;
        return;
    }
    r -= ONEHOT_E;
    if (r < T_TOKENS) { outp[off] = g_top1[r]; return; }
    r -= T_TOKENS;
    if (r < PROBS_E) { outp[off] = g_probs[r]; return; }
    r -= PROBS_E;
    if (r == 0) { outp[off] = g_aux; return; }
    outp[off] = (float)g_dropped;
}

// ---------------- launch ----------------
extern "C" void kernel_launch(void* const* d_in, const int* in_sizes, int n_in,
                              void* d_out, int out_size) {
    const float* x  = (const float*)d_in[0];
    const float* Wr = (const float*)d_in[1];
    const float* br = (const float*)d_in[2];
    const float* Wi = (const float*)d_in[3];
    const float* Wo = (const float*)d_in[4];
    float* outp = (float*)d_out;

    zero_kernel<<<1, 32>>>();
    router_kernel<<<T_TOKENS / 8, 256>>>(x, Wr, br);
    count_kernel<<<NB, 1024>>>();
    scan_kernel<<<1, 32>>>();
    rank_kernel<<<NB, 1024>>>();

    dim3 g1(D_FF / 128, CAPACITY / 128, N_EXPERTS);
    gemm_mma<D_MODEL, true, true><<<g1, 512>>>(x, Wi, nullptr);
    dim3 g2(D_MODEL / 128, CAPACITY / 128, N_EXPERTS);
    gemm_mma<D_FF, false, false><<<g2, 512>>>(nullptr, Wo, outp);

    drop_kernel<<<256, 256>>>(outp);

    long long extra = (long long)out_size - OUT_ELEMS;
    if (extra > 0) {
        unsigned nb = (unsigned)((extra + 255) / 256);
        extras_kernel<<<nb, 256>>>(outp, (long long)out_size);
    }
}

// round 6
// speedup vs baseline: 2.4181x; 1.1737x over previous
#include <cuda_runtime.h>
#include <math.h>
#include <stdint.h>

#define D_MODEL   512
#define D_FF      2048
#define N_EXPERTS 8
#define CAPACITY  10240
#define T_TOKENS  65536
#define NB        64

#define OUT_ELEMS   ((long long)T_TOKENS * D_MODEL)
#define ONEHOT_E    ((long long)T_TOKENS * N_EXPERTS)
#define PROBS_E     ((long long)T_TOKENS * N_EXPERTS)

// GEMM smem layout (dynamic): 4-stage, 128 rows x 20 floats per operand stage
#define LDS_F     20
#define STAGE_F   (128 * LDS_F)            // 2560 floats
#define STAGE_B4  (STAGE_F * 4)            // 10240 bytes
#define SMEM_GEMM (8 * STAGE_B4 + 512 + 128)

// ---------------- scratch ----------------
__device__ float g_probs[T_TOKENS * N_EXPERTS];
__device__ float g_top1[T_TOKENS];
__device__ int   g_expert[T_TOKENS];
__device__ int   g_pos[T_TOKENS];
__device__ int   g_blockCounts[NB * N_EXPERTS];
__device__ int   g_blockOffsets[NB * N_EXPERTS];
__device__ int   g_total[N_EXPERTS];
__device__ float g_pi_sum[N_EXPERTS];
__device__ float g_aux;
__device__ int   g_dropped;
__device__ int   g_slot2tok[N_EXPERTS * CAPACITY];
__device__ float g_xt[(size_t)T_TOKENS * D_MODEL];               // tf32-rounded x
__device__ float g_Wit[(size_t)N_EXPERTS * D_FF * D_MODEL];      // tf32-rounded Wi
__device__ float g_Wot[(size_t)N_EXPERTS * D_MODEL * D_FF];      // tf32-rounded Wo
__device__ float g_H[(size_t)N_EXPERTS * CAPACITY * D_FF];

// ---------------- helpers ----------------
__device__ __forceinline__ uint32_t s2u(const void* p) {
    uint32_t a;
    asm("{ .reg .u64 t; cvta.to.shared.u64 t, %1; cvt.u32.u64 %0, t; }" : "=r"(a) : "l"(p));
    return a;
}
__device__ __forceinline__ void cpasync16(uint32_t saddr, const void* gaddr) {
    asm volatile("cp.async.cg.shared.global [%0], [%1], 16;" :: "r"(saddr), "l"(gaddr) : "memory");
}
__device__ __forceinline__ float tf32r(float x) {
    uint32_t u; asm("cvt.rna.tf32.f32 %0, %1;" : "=r"(u) : "f"(x));
    return __uint_as_float(u);
}
__device__ __forceinline__ void mma8(float* c, const uint32_t* a, const uint32_t* b) {
    asm volatile(
        "mma.sync.aligned.m16n8k8.row.col.f32.tf32.tf32.f32 "
        "{%0,%1,%2,%3}, {%4,%5,%6,%7}, {%8,%9}, {%0,%1,%2,%3};"
        : "+f"(c[0]), "+f"(c[1]), "+f"(c[2]), "+f"(c[3])
        : "r"(a[0]), "r"(a[1]), "r"(a[2]), "r"(a[3]), "r"(b[0]), "r"(b[1]));
}

// ---------------- pre-round inputs to tf32 (once per call) ----------------
__global__ void round_x_kernel(const float4* __restrict__ s) {
    int i = blockIdx.x * 256 + threadIdx.x;
    float4 v = s[i];
    v.x = tf32r(v.x); v.y = tf32r(v.y); v.z = tf32r(v.z); v.w = tf32r(v.w);
    ((float4*)g_xt)[i] = v;
}
__global__ void round_wi_kernel(const float4* __restrict__ s) {
    int i = blockIdx.x * 256 + threadIdx.x;
    float4 v = s[i];
    v.x = tf32r(v.x); v.y = tf32r(v.y); v.z = tf32r(v.z); v.w = tf32r(v.w);
    ((float4*)g_Wit)[i] = v;
}
__global__ void round_wo_kernel(const float4* __restrict__ s) {
    int i = blockIdx.x * 256 + threadIdx.x;
    float4 v = s[i];
    v.x = tf32r(v.x); v.y = tf32r(v.y); v.z = tf32r(v.z); v.w = tf32r(v.w);
    ((float4*)g_Wot)[i] = v;
}

// ---------------- routing (known-correct from R1) ----------------
__global__ void zero_kernel() {
    int i = threadIdx.x;
    if (i < N_EXPERTS) g_pi_sum[i] = 0.f;
}

__global__ void router_kernel(const float* __restrict__ x,
                              const float* __restrict__ Wr,
                              const float* __restrict__ br) {
    __shared__ float Ws[N_EXPERTS * D_MODEL];
    __shared__ float brs[N_EXPERTS];
    __shared__ float pis[N_EXPERTS];
    int tid = threadIdx.x;
    for (int i = tid; i < N_EXPERTS * D_MODEL; i += 256) Ws[i] = Wr[i];
    if (tid < N_EXPERTS) { brs[tid] = br[tid]; pis[tid] = 0.f; }
    __syncthreads();

    int warp = tid >> 5, lane = tid & 31;
    int t = blockIdx.x * 8 + warp;

    float acc[N_EXPERTS];
#pragma unroll
    for (int e = 0; e < N_EXPERTS; e++) acc[e] = 0.f;
    const float* xr = x + (size_t)t * D_MODEL;
#pragma unroll
    for (int i = 0; i < D_MODEL / 32; i++) {
        int c = lane + i * 32;
        float v = xr[c];
#pragma unroll
        for (int e = 0; e < N_EXPERTS; e++) acc[e] += v * Ws[e * D_MODEL + c];
    }
#pragma unroll
    for (int e = 0; e < N_EXPERTS; e++) {
#pragma unroll
        for (int off = 16; off > 0; off >>= 1)
            acc[e] += __shfl_down_sync(0xffffffffu, acc[e], off);
    }
    if (lane == 0) {
        float l[N_EXPERTS];
        float mx = -INFINITY; int idx = 0;
#pragma unroll
        for (int e = 0; e < N_EXPERTS; e++) {
            l[e] = acc[e] + brs[e];
            if (l[e] > mx) { mx = l[e]; idx = e; }
        }
        float s = 0.f, pr[N_EXPERTS];
#pragma unroll
        for (int e = 0; e < N_EXPERTS; e++) { pr[e] = expf(l[e] - mx); s += pr[e]; }
        float inv = 1.f / s;
#pragma unroll
        for (int e = 0; e < N_EXPERTS; e++) {
            float p = pr[e] * inv;
            g_probs[(size_t)t * N_EXPERTS + e] = p;
            atomicAdd(&pis[e], p);
        }
        g_top1[t] = pr[idx] * inv;
        g_expert[t] = idx;
    }
    __syncthreads();
    if (tid < N_EXPERTS) atomicAdd(&g_pi_sum[tid], pis[tid]);
}

__global__ void count_kernel() {
    __shared__ int c[N_EXPERTS];
    if (threadIdx.x < N_EXPERTS) c[threadIdx.x] = 0;
    __syncthreads();
    int t = blockIdx.x * 1024 + threadIdx.x;
    atomicAdd(&c[g_expert[t]], 1);
    __syncthreads();
    if (threadIdx.x < N_EXPERTS)
        g_blockCounts[blockIdx.x * N_EXPERTS + threadIdx.x] = c[threadIdx.x];
}

__global__ void scan_kernel() {
    int e = threadIdx.x;
    if (e < N_EXPERTS) {
        int run = 0;
        for (int b = 0; b < NB; b++) {
            g_blockOffsets[b * N_EXPERTS + e] = run;
            run += g_blockCounts[b * N_EXPERTS + e];
        }
        g_total[e] = run;
    }
    __syncthreads();
    if (e == 0) {
        float aux = 0.f; int drop = 0;
        for (int k = 0; k < N_EXPERTS; k++) {
            int tot = g_total[k];
            int kept = tot < CAPACITY ? tot : CAPACITY;
            drop += tot - kept;
            float fi = (float)kept / (float)T_TOKENS;
            float pi = g_pi_sum[k] / (float)T_TOKENS;
            aux += fi * pi;
        }
        g_aux = aux * (float)N_EXPERTS;
        g_dropped = drop;
    }
}

__global__ void rank_kernel() {
    __shared__ int warpCnt[32][N_EXPERTS];
    __shared__ int warpOff[32][N_EXPERTS];
    int tid = threadIdx.x, w = tid >> 5, lane = tid & 31;
    int t = blockIdx.x * 1024 + tid;
    int e = g_expert[t];
    unsigned lt = (lane == 0) ? 0u : (0xffffffffu >> (32 - lane));
    int myrank = 0;
#pragma unroll
    for (int k = 0; k < N_EXPERTS; k++) {
        unsigned m = __ballot_sync(0xffffffffu, e == k);
        if (lane == 0) warpCnt[w][k] = __popc(m);
        if (e == k) myrank = __popc(m & lt);
    }
    __syncthreads();
    if (tid < 32 * N_EXPERTS) {
        int ww = tid >> 3, k = tid & 7;
        int s = 0;
        for (int u = 0; u < ww; u++) s += warpCnt[u][k];
        warpOff[ww][k] = s;
    }
    __syncthreads();
    int pos = g_blockOffsets[blockIdx.x * N_EXPERTS + e] + warpOff[w][e] + myrank;
    g_pos[t] = pos;
    if (pos < CAPACITY) g_slot2tok[e * CAPACITY + pos] = t;
}

// ---------------- tf32 mma.sync GEMM, 4-stage cp.async pipeline ----------------
// All global scratch referenced INSIDE the kernel (device symbols are not
// valid host-side arguments!).  GATHER: A = g_xt[slot2tok], B = g_Wit, D = g_H.
// else: A = g_H slots, B = g_Wot, D = outp (arg) scaled by top1, scattered.
template<int K_TOT, bool GATHER, bool RELU>
__global__ void __launch_bounds__(512, 1)
gemm_mma(float* __restrict__ Dglob) {
    constexpr int BK = 16;
    extern __shared__ float smem[];
    float* sA = smem;                       // 4 stages
    float* sB = smem + 4 * STAGE_F;         // 4 stages
    int* tokS = (int*)(smem + 8 * STAGE_F);

    int e = blockIdx.z;
    int ne = g_total[e]; if (ne > CAPACITY) ne = CAPACITY;
    int m0 = blockIdx.y * 128;
    if (m0 >= ne) return;
    int n0 = blockIdx.x * 128;

    int tid = threadIdx.x;
    int wid = tid >> 5, lane = tid & 31;
    int wm = wid >> 2, wn = wid & 3;

    if (GATHER && tid < 128) {
        int m = m0 + tid;
        tokS[tid] = (m < ne) ? g_slot2tok[e * CAPACITY + m] : 0;
    }
    __syncthreads();

    const float* Bbase = (RELU ? g_Wit : g_Wot) +
        ((size_t)e * (RELU ? D_FF : D_MODEL) + n0) * K_TOT;
    const float* Hbase = g_H + ((size_t)e * CAPACITY + m0) * (size_t)D_FF;

    // loader: 512 threads, 1 float4 of A + 1 of B per stage
    int lrow = tid >> 2, lq = tid & 3;
    const float* aRowPtr;
    if (GATHER) aRowPtr = g_xt + (size_t)tokS[lrow] * D_MODEL + lq * 4;
    else        aRowPtr = Hbase + (size_t)lrow * D_FF + lq * 4;
    const float* bRowPtr = Bbase + (size_t)lrow * K_TOT + lq * 4;
    uint32_t sAu = s2u(sA) + (lrow * LDS_F + lq * 4) * 4;
    uint32_t sBu = s2u(sB) + (lrow * LDS_F + lq * 4) * 4;

    float acc[2][4][4];
#pragma unroll
    for (int mi = 0; mi < 2; mi++)
#pragma unroll
        for (int ni = 0; ni < 4; ni++)
#pragma unroll
            for (int r = 0; r < 4; r++) acc[mi][ni][r] = 0.f;

    const int NS = K_TOT / BK;
    // prologue: stages 0..2 in flight
#pragma unroll
    for (int s = 0; s < 3; s++) {
        cpasync16(sAu + s * STAGE_B4, aRowPtr + s * BK);
        cpasync16(sBu + s * STAGE_B4, bRowPtr + s * BK);
        asm volatile("cp.async.commit_group;" ::: "memory");
    }

    for (int s = 0; s < NS; s++) {
        asm volatile("cp.async.wait_group 2;" ::: "memory");
        __syncthreads();
        int sl = s & 3;
        if (s + 3 < NS) {
            int nb = (s + 3) & 3;
            cpasync16(sAu + nb * STAGE_B4, aRowPtr + (s + 3) * BK);
            cpasync16(sBu + nb * STAGE_B4, bRowPtr + (s + 3) * BK);
        }
        asm volatile("cp.async.commit_group;" ::: "memory");

        const float* A = sA + sl * STAGE_F;
        const float* B = sB + sl * STAGE_F;
#pragma unroll
        for (int kf = 0; kf < 2; kf++) {
            int kc = kf * 8 + (lane & 3);
            uint32_t a[2][4], b[4][2];
#pragma unroll
            for (int mi = 0; mi < 2; mi++) {
                int r = wm * 32 + mi * 16 + (lane >> 2);
                a[mi][0] = __float_as_uint(A[r * LDS_F + kc]);
                a[mi][1] = __float_as_uint(A[(r + 8) * LDS_F + kc]);
                a[mi][2] = __float_as_uint(A[r * LDS_F + kc + 4]);
                a[mi][3] = __float_as_uint(A[(r + 8) * LDS_F + kc + 4]);
            }
#pragma unroll
            for (int ni = 0; ni < 4; ni++) {
                int r = wn * 32 + ni * 8 + (lane >> 2);
                b[ni][0] = __float_as_uint(B[r * LDS_F + kc]);
                b[ni][1] = __float_as_uint(B[r * LDS_F + kc + 4]);
            }
#pragma unroll
            for (int mi = 0; mi < 2; mi++)
#pragma unroll
                for (int ni = 0; ni < 4; ni++)
                    mma8(acc[mi][ni], a[mi], b[ni]);
        }
    }

    // epilogue
#pragma unroll
    for (int mi = 0; mi < 2; mi++) {
#pragma unroll
        for (int half = 0; half < 2; half++) {
            int m = m0 + wm * 32 + mi * 16 + (lane >> 2) + half * 8;
            bool valid = m < ne;
            float sc = 1.f;
            float* rowptr;
            if (RELU) {
                rowptr = g_H + ((size_t)e * CAPACITY + m) * D_FF + n0;
            } else {
                int tk = valid ? g_slot2tok[e * CAPACITY + m] : 0;
                sc = g_top1[tk];
                rowptr = Dglob + (size_t)tk * D_MODEL + n0;
            }
            if (valid) {
#pragma unroll
                for (int ni = 0; ni < 4; ni++) {
                    int c = wn * 32 + ni * 8 + 2 * (lane & 3);
                    float v0 = acc[mi][ni][half * 2 + 0];
                    float v1 = acc[mi][ni][half * 2 + 1];
                    float2 v;
                    if (RELU) {
                        v.x = tf32r(fmaxf(v0, 0.f));
                        v.y = tf32r(fmaxf(v1, 0.f));
                    } else {
                        v.x = v0 * sc;
                        v.y = v1 * sc;
                    }
                    *(float2*)(rowptr + c) = v;
                }
            }
        }
    }
}

__global__ void drop_kernel(float* __restrict__ outp) {
    for (int t = blockIdx.x * blockDim.x + threadIdx.x; t < T_TOKENS;
         t += gridDim.x * blockDim.x) {
        if (g_pos[t] >= CAPACITY) {
            float4 z = make_float4(0.f, 0.f, 0.f, 0.f);
            float4* p = (float4*)(outp + (size_t)t * D_MODEL);
            for (int i = 0; i < D_MODEL / 4; i++) p[i] = z;
        }
    }
}

__global__ void extras_kernel(float* __restrict__ outp, long long out_size) {
    long long i = (long long)blockIdx.x * blockDim.x + threadIdx.x;
    long long off = OUT_ELEMS + i;
    if (off >= out_size) return;
    long long r = i;
    if (r < ONEHOT_E) {
        int t = (int)(r >> 3), e = (int)(r & 7);
        outp[off] = (g_expert[t] == e && g_pos[t] < CAPACITY) ? 1.f : 0.f;
        return;
    }
    r -= ONEHOT_E;
    if (r < T_TOKENS) { outp[off] = g_top1[r]; return; }
    r -= T_TOKENS;
    if (r < PROBS_E) { outp[off] = g_probs[r]; return; }
    r -= PROBS_E;
    if (r == 0) { outp[off] = g_aux; return; }
    outp[off] = (float)g_dropped;
}

// ---------------- launch ----------------
extern "C" void kernel_launch(void* const* d_in, const int* in_sizes, int n_in,
                              void* d_out, int out_size) {
    const float* x  = (const float*)d_in[0];
    const float* Wr = (const float*)d_in[1];
    const float* br = (const float*)d_in[2];
    const float* Wi = (const float*)d_in[3];
    const float* Wo = (const float*)d_in[4];
    float* outp = (float*)d_out;

    cudaFuncSetAttribute(gemm_mma<D_MODEL, true, true>,
                         cudaFuncAttributeMaxDynamicSharedMemorySize, SMEM_GEMM);
    cudaFuncSetAttribute(gemm_mma<D_FF, false, false>,
                         cudaFuncAttributeMaxDynamicSharedMemorySize, SMEM_GEMM);

    zero_kernel<<<1, 32>>>();
    router_kernel<<<T_TOKENS / 8, 256>>>(x, Wr, br);
    count_kernel<<<NB, 1024>>>();
    scan_kernel<<<1, 32>>>();
    rank_kernel<<<NB, 1024>>>();

    round_x_kernel<<<(T_TOKENS * D_MODEL / 4) / 256, 256>>>((const float4*)x);
    round_wi_kernel<<<(int)(((size_t)N_EXPERTS * D_FF * D_MODEL / 4) / 256), 256>>>((const float4*)Wi);
    round_wo_kernel<<<(int)(((size_t)N_EXPERTS * D_MODEL * D_FF / 4) / 256), 256>>>((const float4*)Wo);

    dim3 g1(D_FF / 128, CAPACITY / 128, N_EXPERTS);
    gemm_mma<D_MODEL, true, true><<<g1, 512, SMEM_GEMM>>>(nullptr);
    dim3 g2(D_MODEL / 128, CAPACITY / 128, N_EXPERTS);
    gemm_mma<D_FF, false, false><<<g2, 512, SMEM_GEMM>>>(outp);

    drop_kernel<<<256, 256>>>(outp);

    long long extra = (long long)out_size - OUT_ELEMS;
    if (extra > 0) {
        unsigned nb = (unsigned)((extra + 255) / 256);
        extras_kernel<<<nb, 256>>>(outp, (long long)out_size);
    }
}

// round 7
// speedup vs baseline: 2.6765x; 1.1069x over previous
#include <cuda_runtime.h>
#include <math.h>
#include <stdint.h>

#define D_MODEL   512
#define D_FF      2048
#define N_EXPERTS 8
#define CAPACITY  10240
#define T_TOKENS  65536
#define NB        64

#define OUT_ELEMS   ((long long)T_TOKENS * D_MODEL)
#define ONEHOT_E    ((long long)T_TOKENS * N_EXPERTS)
#define PROBS_E     ((long long)T_TOKENS * N_EXPERTS)

// GEMM smem: 4-stage, 128 rows x 24 floats (16 data + 8 pad) per operand stage.
// Stride 24 floats => (24*q + 2*j) mod 32 covers all banks: conflict-free LDS.64.
#define LDS_F     24
#define STAGE_F   (128 * LDS_F)            // 3072 floats
#define STAGE_B4  (STAGE_F * 4)            // 12288 bytes
#define SMEM_GEMM (8 * STAGE_B4 + 512 + 128)

// ---------------- scratch ----------------
__device__ float g_probs[T_TOKENS * N_EXPERTS];
__device__ float g_top1[T_TOKENS];
__device__ int   g_expert[T_TOKENS];
__device__ int   g_pos[T_TOKENS];
__device__ int   g_blockCounts[NB * N_EXPERTS];
__device__ int   g_blockOffsets[NB * N_EXPERTS];
__device__ int   g_total[N_EXPERTS];
__device__ float g_pi_sum[N_EXPERTS];
__device__ float g_aux;
__device__ int   g_dropped;
__device__ int   g_slot2tok[N_EXPERTS * CAPACITY];
// k-interleaved (within 8-groups: k -> (k%4)*2 + k/4), tf32-rounded operands
__device__ float g_xt[(size_t)T_TOKENS * D_MODEL];
__device__ float g_Wit[(size_t)N_EXPERTS * D_FF * D_MODEL];
__device__ float g_Wot[(size_t)N_EXPERTS * D_MODEL * D_FF];
__device__ float g_H[(size_t)N_EXPERTS * CAPACITY * D_FF];

// ---------------- helpers ----------------
__device__ __forceinline__ uint32_t s2u(const void* p) {
    uint32_t a;
    asm("{ .reg .u64 t; cvta.to.shared.u64 t, %1; cvt.u32.u64 %0, t; }" : "=r"(a) : "l"(p));
    return a;
}
__device__ __forceinline__ void cpasync16(uint32_t saddr, const void* gaddr) {
    asm volatile("cp.async.cg.shared.global [%0], [%1], 16;" :: "r"(saddr), "l"(gaddr) : "memory");
}
__device__ __forceinline__ float tf32r(float x) {
    uint32_t u; asm("cvt.rna.tf32.f32 %0, %1;" : "=r"(u) : "f"(x));
    return __uint_as_float(u);
}
__device__ __forceinline__ void mma8(float* c, uint32_t a0, uint32_t a1, uint32_t a2,
                                     uint32_t a3, uint32_t b0, uint32_t b1) {
    asm volatile(
        "mma.sync.aligned.m16n8k8.row.col.f32.tf32.tf32.f32 "
        "{%0,%1,%2,%3}, {%4,%5,%6,%7}, {%8,%9}, {%0,%1,%2,%3};"
        : "+f"(c[0]), "+f"(c[1]), "+f"(c[2]), "+f"(c[3])
        : "r"(a0), "r"(a1), "r"(a2), "r"(a3), "r"(b0), "r"(b1));
}

// ---------------- pre-round + k-interleave (once per call) ----------------
// Each thread handles one float4 = 4 consecutive k within one 8-group half.
template<int WHICH>
__global__ void round_perm_kernel(const float4* __restrict__ s) {
    long long i = (long long)blockIdx.x * 256 + threadIdx.x;
    float4 v = s[i];
    long long base = i * 4;
    int j = (int)(base & 7);            // 0 or 4
    long long g0 = base - j;            // 8-group start
    float* dst = (WHICH == 0) ? g_xt : (WHICH == 1) ? g_Wit : g_Wot;
    float vals[4] = {v.x, v.y, v.z, v.w};
#pragma unroll
    for (int u = 0; u < 4; u++) {
        int k8 = j + u;
        int p = ((k8 & 3) << 1) | (k8 >> 2);
        dst[g0 + p] = tf32r(vals[u]);
    }
}

// ---------------- routing (known-correct from R1) ----------------
__global__ void zero_kernel() {
    int i = threadIdx.x;
    if (i < N_EXPERTS) g_pi_sum[i] = 0.f;
}

__global__ void router_kernel(const float* __restrict__ x,
                              const float* __restrict__ Wr,
                              const float* __restrict__ br) {
    __shared__ float Ws[N_EXPERTS * D_MODEL];
    __shared__ float brs[N_EXPERTS];
    __shared__ float pis[N_EXPERTS];
    int tid = threadIdx.x;
    for (int i = tid; i < N_EXPERTS * D_MODEL; i += 256) Ws[i] = Wr[i];
    if (tid < N_EXPERTS) { brs[tid] = br[tid]; pis[tid] = 0.f; }
    __syncthreads();

    int warp = tid >> 5, lane = tid & 31;
    int t = blockIdx.x * 8 + warp;

    float acc[N_EXPERTS];
#pragma unroll
    for (int e = 0; e < N_EXPERTS; e++) acc[e] = 0.f;
    const float* xr = x + (size_t)t * D_MODEL;
#pragma unroll
    for (int i = 0; i < D_MODEL / 32; i++) {
        int c = lane + i * 32;
        float v = xr[c];
#pragma unroll
        for (int e = 0; e < N_EXPERTS; e++) acc[e] += v * Ws[e * D_MODEL + c];
    }
#pragma unroll
    for (int e = 0; e < N_EXPERTS; e++) {
#pragma unroll
        for (int off = 16; off > 0; off >>= 1)
            acc[e] += __shfl_down_sync(0xffffffffu, acc[e], off);
    }
    if (lane == 0) {
        float l[N_EXPERTS];
        float mx = -INFINITY; int idx = 0;
#pragma unroll
        for (int e = 0; e < N_EXPERTS; e++) {
            l[e] = acc[e] + brs[e];
            if (l[e] > mx) { mx = l[e]; idx = e; }
        }
        float s = 0.f, pr[N_EXPERTS];
#pragma unroll
        for (int e = 0; e < N_EXPERTS; e++) { pr[e] = expf(l[e] - mx); s += pr[e]; }
        float inv = 1.f / s;
#pragma unroll
        for (int e = 0; e < N_EXPERTS; e++) {
            float p = pr[e] * inv;
            g_probs[(size_t)t * N_EXPERTS + e] = p;
            atomicAdd(&pis[e], p);
        }
        g_top1[t] = pr[idx] * inv;
        g_expert[t] = idx;
    }
    __syncthreads();
    if (tid < N_EXPERTS) atomicAdd(&g_pi_sum[tid], pis[tid]);
}

__global__ void count_kernel() {
    __shared__ int c[N_EXPERTS];
    if (threadIdx.x < N_EXPERTS) c[threadIdx.x] = 0;
    __syncthreads();
    int t = blockIdx.x * 1024 + threadIdx.x;
    atomicAdd(&c[g_expert[t]], 1);
    __syncthreads();
    if (threadIdx.x < N_EXPERTS)
        g_blockCounts[blockIdx.x * N_EXPERTS + threadIdx.x] = c[threadIdx.x];
}

__global__ void scan_kernel() {
    int e = threadIdx.x;
    if (e < N_EXPERTS) {
        int run = 0;
        for (int b = 0; b < NB; b++) {
            g_blockOffsets[b * N_EXPERTS + e] = run;
            run += g_blockCounts[b * N_EXPERTS + e];
        }
        g_total[e] = run;
    }
    __syncthreads();
    if (e == 0) {
        float aux = 0.f; int drop = 0;
        for (int k = 0; k < N_EXPERTS; k++) {
            int tot = g_total[k];
            int kept = tot < CAPACITY ? tot : CAPACITY;
            drop += tot - kept;
            float fi = (float)kept / (float)T_TOKENS;
            float pi = g_pi_sum[k] / (float)T_TOKENS;
            aux += fi * pi;
        }
        g_aux = aux * (float)N_EXPERTS;
        g_dropped = drop;
    }
}

__global__ void rank_kernel() {
    __shared__ int warpCnt[32][N_EXPERTS];
    __shared__ int warpOff[32][N_EXPERTS];
    int tid = threadIdx.x, w = tid >> 5, lane = tid & 31;
    int t = blockIdx.x * 1024 + tid;
    int e = g_expert[t];
    unsigned lt = (lane == 0) ? 0u : (0xffffffffu >> (32 - lane));
    int myrank = 0;
#pragma unroll
    for (int k = 0; k < N_EXPERTS; k++) {
        unsigned m = __ballot_sync(0xffffffffu, e == k);
        if (lane == 0) warpCnt[w][k] = __popc(m);
        if (e == k) myrank = __popc(m & lt);
    }
    __syncthreads();
    if (tid < 32 * N_EXPERTS) {
        int ww = tid >> 3, k = tid & 7;
        int s = 0;
        for (int u = 0; u < ww; u++) s += warpCnt[u][k];
        warpOff[ww][k] = s;
    }
    __syncthreads();
    int pos = g_blockOffsets[blockIdx.x * N_EXPERTS + e] + warpOff[w][e] + myrank;
    g_pos[t] = pos;
    if (pos < CAPACITY) g_slot2tok[e * CAPACITY + pos] = t;
}

// ---------------- tf32 mma.sync GEMM, LDS.64 fragments ----------------
template<int K_TOT, bool GATHER, bool RELU>
__global__ void __launch_bounds__(512, 1)
gemm_mma(float* __restrict__ Dglob) {
    constexpr int BK = 16;
    extern __shared__ float smem[];
    float* sA = smem;
    float* sB = smem + 4 * STAGE_F;
    int* tokS = (int*)(smem + 8 * STAGE_F);

    int e = blockIdx.z;
    int ne = g_total[e]; if (ne > CAPACITY) ne = CAPACITY;
    int m0 = blockIdx.y * 128;
    if (m0 >= ne) return;
    int n0 = blockIdx.x * 128;

    int tid = threadIdx.x;
    int wid = tid >> 5, lane = tid & 31;
    int wm = wid >> 2, wn = wid & 3;
    int qr = lane >> 2, j = lane & 3;

    if (GATHER && tid < 128) {
        int m = m0 + tid;
        tokS[tid] = (m < ne) ? g_slot2tok[e * CAPACITY + m] : 0;
    }
    __syncthreads();

    const float* Bbase = (RELU ? g_Wit : g_Wot) +
        ((size_t)e * (RELU ? D_FF : D_MODEL) + n0) * K_TOT;
    const float* Hbase = g_H + ((size_t)e * CAPACITY + m0) * (size_t)D_FF;

    int lrow = tid >> 2, lq = tid & 3;
    const float* aRowPtr;
    if (GATHER) aRowPtr = g_xt + (size_t)tokS[lrow] * D_MODEL + lq * 4;
    else        aRowPtr = Hbase + (size_t)lrow * D_FF + lq * 4;
    const float* bRowPtr = Bbase + (size_t)lrow * K_TOT + lq * 4;
    uint32_t sAu = s2u(sA) + (lrow * LDS_F + lq * 4) * 4;
    uint32_t sBu = s2u(sB) + (lrow * LDS_F + lq * 4) * 4;

    float acc[2][4][4];
#pragma unroll
    for (int mi = 0; mi < 2; mi++)
#pragma unroll
        for (int ni = 0; ni < 4; ni++)
#pragma unroll
            for (int r = 0; r < 4; r++) acc[mi][ni][r] = 0.f;

    const int NS = K_TOT / BK;
#pragma unroll
    for (int s = 0; s < 3; s++) {
        cpasync16(sAu + s * STAGE_B4, aRowPtr + s * BK);
        cpasync16(sBu + s * STAGE_B4, bRowPtr + s * BK);
        asm volatile("cp.async.commit_group;" ::: "memory");
    }

    for (int s = 0; s < NS; s++) {
        asm volatile("cp.async.wait_group 2;" ::: "memory");
        __syncthreads();
        int sl = s & 3;
        if (s + 3 < NS) {
            int nb = (s + 3) & 3;
            cpasync16(sAu + nb * STAGE_B4, aRowPtr + (s + 3) * BK);
            cpasync16(sBu + nb * STAGE_B4, bRowPtr + (s + 3) * BK);
        }
        asm volatile("cp.async.commit_group;" ::: "memory");

        const float* A = sA + sl * STAGE_F;
        const float* B = sB + sl * STAGE_F;

        // load ALL fragments for the stage (LDS.64, conflict-free)
        uint2 af[2][2][2];   // [kf][mi][rowhalf] = (k, k+4)
        uint2 bf[2][4];      // [kf][ni]
#pragma unroll
        for (int kf = 0; kf < 2; kf++) {
            int co = kf * 8 + 2 * j;   // interleaved offset
#pragma unroll
            for (int mi = 0; mi < 2; mi++) {
                int r = wm * 32 + mi * 16 + qr;
                af[kf][mi][0] = *(const uint2*)&A[r * LDS_F + co];
                af[kf][mi][1] = *(const uint2*)&A[(r + 8) * LDS_F + co];
            }
#pragma unroll
            for (int ni = 0; ni < 4; ni++) {
                int r = wn * 32 + ni * 8 + qr;
                bf[kf][ni] = *(const uint2*)&B[r * LDS_F + co];
            }
        }
#pragma unroll
        for (int kf = 0; kf < 2; kf++)
#pragma unroll
            for (int mi = 0; mi < 2; mi++)
#pragma unroll
                for (int ni = 0; ni < 4; ni++)
                    mma8(acc[mi][ni],
                         af[kf][mi][0].x, af[kf][mi][1].x,
                         af[kf][mi][0].y, af[kf][mi][1].y,
                         bf[kf][ni].x, bf[kf][ni].y);
    }

    // epilogue
    int j2 = 2 * j;
    int p0 = ((j2 & 3) << 1) | (j2 >> 2);          // perm pos of col 2j
    int p1 = (((j2 + 1) & 3) << 1) | ((j2 + 1) >> 2);  // perm pos of col 2j+1
#pragma unroll
    for (int mi = 0; mi < 2; mi++) {
#pragma unroll
        for (int half = 0; half < 2; half++) {
            int m = m0 + wm * 32 + mi * 16 + qr + half * 8;
            bool valid = m < ne;
            float sc = 1.f;
            float* rowptr;
            if (RELU) {
                rowptr = g_H + ((size_t)e * CAPACITY + m) * D_FF + n0;
            } else {
                int tk = valid ? g_slot2tok[e * CAPACITY + m] : 0;
                sc = g_top1[tk];
                rowptr = Dglob + (size_t)tk * D_MODEL + n0;
            }
            if (valid) {
#pragma unroll
                for (int ni = 0; ni < 4; ni++) {
                    float v0 = acc[mi][ni][half * 2 + 0];
                    float v1 = acc[mi][ni][half * 2 + 1];
                    if (RELU) {
                        // H consumed as GEMM2 A-operand: store k-interleaved
                        int cb = wn * 32 + ni * 8;
                        rowptr[cb + p0] = tf32r(fmaxf(v0, 0.f));
                        rowptr[cb + p1] = tf32r(fmaxf(v1, 0.f));
                    } else {
                        int c = wn * 32 + ni * 8 + j2;
                        float2 v; v.x = v0 * sc; v.y = v1 * sc;
                        *(float2*)(rowptr + c) = v;
                    }
                }
            }
        }
    }
}

__global__ void drop_kernel(float* __restrict__ outp) {
    for (int t = blockIdx.x * blockDim.x + threadIdx.x; t < T_TOKENS;
         t += gridDim.x * blockDim.x) {
        if (g_pos[t] >= CAPACITY) {
            float4 z = make_float4(0.f, 0.f, 0.f, 0.f);
            float4* p = (float4*)(outp + (size_t)t * D_MODEL);
            for (int i = 0; i < D_MODEL / 4; i++) p[i] = z;
        }
    }
}

__global__ void extras_kernel(float* __restrict__ outp, long long out_size) {
    long long i = (long long)blockIdx.x * blockDim.x + threadIdx.x;
    long long off = OUT_ELEMS + i;
    if (off >= out_size) return;
    long long r = i;
    if (r < ONEHOT_E) {
        int t = (int)(r >> 3), e = (int)(r & 7);
        outp[off] = (g_expert[t] == e && g_pos[t] < CAPACITY) ? 1.f : 0.f;
        return;
    }
    r -= ONEHOT_E;
    if (r < T_TOKENS) { outp[off] = g_top1[r]; return; }
    r -= T_TOKENS;
    if (r < PROBS_E) { outp[off] = g_probs[r]; return; }
    r -= PROBS_E;
    if (r == 0) { outp[off] = g_aux; return; }
    outp[off] = (float)g_dropped;
}

// ---------------- launch ----------------
extern "C" void kernel_launch(void* const* d_in, const int* in_sizes, int n_in,
                              void* d_out, int out_size) {
    const float* x  = (const float*)d_in[0];
    const float* Wr = (const float*)d_in[1];
    const float* br = (const float*)d_in[2];
    const float* Wi = (const float*)d_in[3];
    const float* Wo = (const float*)d_in[4];
    float* outp = (float*)d_out;

    cudaFuncSetAttribute(gemm_mma<D_MODEL, true, true>,
                         cudaFuncAttributeMaxDynamicSharedMemorySize, SMEM_GEMM);
    cudaFuncSetAttribute(gemm_mma<D_FF, false, false>,
                         cudaFuncAttributeMaxDynamicSharedMemorySize, SMEM_GEMM);

    zero_kernel<<<1, 32>>>();
    router_kernel<<<T_TOKENS / 8, 256>>>(x, Wr, br);
    count_kernel<<<NB, 1024>>>();
    scan_kernel<<<1, 32>>>();
    rank_kernel<<<NB, 1024>>>();

    round_perm_kernel<0><<<(unsigned)((T_TOKENS * (long long)D_MODEL / 4) / 256), 256>>>((const float4*)x);
    round_perm_kernel<1><<<(unsigned)(((long long)N_EXPERTS * D_FF * D_MODEL / 4) / 256), 256>>>((const float4*)Wi);
    round_perm_kernel<2><<<(unsigned)(((long long)N_EXPERTS * D_MODEL * D_FF / 4) / 256), 256>>>((const float4*)Wo);

    dim3 g1(D_FF / 128, CAPACITY / 128, N_EXPERTS);
    gemm_mma<D_MODEL, true, true><<<g1, 512, SMEM_GEMM>>>(nullptr);
    dim3 g2(D_MODEL / 128, CAPACITY / 128, N_EXPERTS);
    gemm_mma<D_FF, false, false><<<g2, 512, SMEM_GEMM>>>(outp);

    drop_kernel<<<256, 256>>>(outp);

    long long extra = (long long)out_size - OUT_ELEMS;
    if (extra > 0) {
        unsigned nb = (unsigned)((extra + 255) / 256);
        extras_kernel<<<nb, 256>>>(outp, (long long)out_size);
    }
}

// round 8
// speedup vs baseline: 2.7230x; 1.0174x over previous
#include <cuda_runtime.h>
#include <math.h>
#include <stdint.h>

#define D_MODEL   512
#define D_FF      2048
#define N_EXPERTS 8
#define CAPACITY  10240
#define T_TOKENS  65536
#define NB        64

#define OUT_ELEMS   ((long long)T_TOKENS * D_MODEL)
#define ONEHOT_E    ((long long)T_TOKENS * N_EXPERTS)
#define PROBS_E     ((long long)T_TOKENS * N_EXPERTS)

// GEMM smem: 3-stage ring, 128 rows x 40 floats (32 data + 8 pad) per operand.
// LDS.64 banks: (40q + 2j + 8kf) mod 32 = (8q + 2j) distinct per 16-lane phase.
#define BK        32
#define LDS_F     40
#define STAGE_F   (128 * LDS_F)            // 5120 floats
#define STAGE_B4  (STAGE_F * 4)            // 20480 bytes
#define SMEM_GEMM (6 * STAGE_B4 + 512 + 128)   // A(3) + B(3) + tokS

// ---------------- scratch ----------------
__device__ float g_probs[T_TOKENS * N_EXPERTS];
__device__ float g_top1[T_TOKENS];
__device__ int   g_expert[T_TOKENS];
__device__ int   g_pos[T_TOKENS];
__device__ int   g_blockCounts[NB * N_EXPERTS];
__device__ int   g_blockOffsets[NB * N_EXPERTS];
__device__ int   g_total[N_EXPERTS];
__device__ float g_pi_sum[N_EXPERTS];
__device__ float g_aux;
__device__ int   g_dropped;
__device__ int   g_slot2tok[N_EXPERTS * CAPACITY];
// k-interleaved (within 8-groups: k -> (k%4)*2 + k/4), tf32-rounded operands
__device__ float g_xt[(size_t)T_TOKENS * D_MODEL];
__device__ float g_Wit[(size_t)N_EXPERTS * D_FF * D_MODEL];
__device__ float g_Wot[(size_t)N_EXPERTS * D_MODEL * D_FF];
__device__ float g_H[(size_t)N_EXPERTS * CAPACITY * D_FF];

// ---------------- helpers ----------------
__device__ __forceinline__ uint32_t s2u(const void* p) {
    uint32_t a;
    asm("{ .reg .u64 t; cvta.to.shared.u64 t, %1; cvt.u32.u64 %0, t; }" : "=r"(a) : "l"(p));
    return a;
}
__device__ __forceinline__ void cpasync16(uint32_t saddr, const void* gaddr) {
    asm volatile("cp.async.cg.shared.global [%0], [%1], 16;" :: "r"(saddr), "l"(gaddr) : "memory");
}
__device__ __forceinline__ float tf32r(float x) {
    uint32_t u; asm("cvt.rna.tf32.f32 %0, %1;" : "=r"(u) : "f"(x));
    return __uint_as_float(u);
}
__device__ __forceinline__ void mma8(float* c, uint32_t a0, uint32_t a1, uint32_t a2,
                                     uint32_t a3, uint32_t b0, uint32_t b1) {
    asm volatile(
        "mma.sync.aligned.m16n8k8.row.col.f32.tf32.tf32.f32 "
        "{%0,%1,%2,%3}, {%4,%5,%6,%7}, {%8,%9}, {%0,%1,%2,%3};"
        : "+f"(c[0]), "+f"(c[1]), "+f"(c[2]), "+f"(c[3])
        : "r"(a0), "r"(a1), "r"(a2), "r"(a3), "r"(b0), "r"(b1));
}

// ---------------- pre-round + k-interleave (once per call) ----------------
template<int WHICH>
__global__ void round_perm_kernel(const float4* __restrict__ s) {
    long long i = (long long)blockIdx.x * 256 + threadIdx.x;
    float4 v = s[i];
    long long base = i * 4;
    int j = (int)(base & 7);            // 0 or 4
    long long g0 = base - j;            // 8-group start
    float* dst = (WHICH == 0) ? g_xt : (WHICH == 1) ? g_Wit : g_Wot;
    float vals[4] = {v.x, v.y, v.z, v.w};
#pragma unroll
    for (int u = 0; u < 4; u++) {
        int k8 = j + u;
        int p = ((k8 & 3) << 1) | (k8 >> 2);
        dst[g0 + p] = tf32r(vals[u]);
    }
}

// ---------------- routing (known-correct from R1) ----------------
__global__ void zero_kernel() {
    int i = threadIdx.x;
    if (i < N_EXPERTS) g_pi_sum[i] = 0.f;
}

__global__ void router_kernel(const float* __restrict__ x,
                              const float* __restrict__ Wr,
                              const float* __restrict__ br) {
    __shared__ float Ws[N_EXPERTS * D_MODEL];
    __shared__ float brs[N_EXPERTS];
    __shared__ float pis[N_EXPERTS];
    int tid = threadIdx.x;
    for (int i = tid; i < N_EXPERTS * D_MODEL; i += 256) Ws[i] = Wr[i];
    if (tid < N_EXPERTS) { brs[tid] = br[tid]; pis[tid] = 0.f; }
    __syncthreads();

    int warp = tid >> 5, lane = tid & 31;
    int t = blockIdx.x * 8 + warp;

    float acc[N_EXPERTS];
#pragma unroll
    for (int e = 0; e < N_EXPERTS; e++) acc[e] = 0.f;
    const float* xr = x + (size_t)t * D_MODEL;
#pragma unroll
    for (int i = 0; i < D_MODEL / 32; i++) {
        int c = lane + i * 32;
        float v = xr[c];
#pragma unroll
        for (int e = 0; e < N_EXPERTS; e++) acc[e] += v * Ws[e * D_MODEL + c];
    }
#pragma unroll
    for (int e = 0; e < N_EXPERTS; e++) {
#pragma unroll
        for (int off = 16; off > 0; off >>= 1)
            acc[e] += __shfl_down_sync(0xffffffffu, acc[e], off);
    }
    if (lane == 0) {
        float l[N_EXPERTS];
        float mx = -INFINITY; int idx = 0;
#pragma unroll
        for (int e = 0; e < N_EXPERTS; e++) {
            l[e] = acc[e] + brs[e];
            if (l[e] > mx) { mx = l[e]; idx = e; }
        }
        float s = 0.f, pr[N_EXPERTS];
#pragma unroll
        for (int e = 0; e < N_EXPERTS; e++) { pr[e] = expf(l[e] - mx); s += pr[e]; }
        float inv = 1.f / s;
#pragma unroll
        for (int e = 0; e < N_EXPERTS; e++) {
            float p = pr[e] * inv;
            g_probs[(size_t)t * N_EXPERTS + e] = p;
            atomicAdd(&pis[e], p);
        }
        g_top1[t] = pr[idx] * inv;
        g_expert[t] = idx;
    }
    __syncthreads();
    if (tid < N_EXPERTS) atomicAdd(&g_pi_sum[tid], pis[tid]);
}

__global__ void count_kernel() {
    __shared__ int c[N_EXPERTS];
    if (threadIdx.x < N_EXPERTS) c[threadIdx.x] = 0;
    __syncthreads();
    int t = blockIdx.x * 1024 + threadIdx.x;
    atomicAdd(&c[g_expert[t]], 1);
    __syncthreads();
    if (threadIdx.x < N_EXPERTS)
        g_blockCounts[blockIdx.x * N_EXPERTS + threadIdx.x] = c[threadIdx.x];
}

__global__ void scan_kernel() {
    int e = threadIdx.x;
    if (e < N_EXPERTS) {
        int run = 0;
        for (int b = 0; b < NB; b++) {
            g_blockOffsets[b * N_EXPERTS + e] = run;
            run += g_blockCounts[b * N_EXPERTS + e];
        }
        g_total[e] = run;
    }
    __syncthreads();
    if (e == 0) {
        float aux = 0.f; int drop = 0;
        for (int k = 0; k < N_EXPERTS; k++) {
            int tot = g_total[k];
            int kept = tot < CAPACITY ? tot : CAPACITY;
            drop += tot - kept;
            float fi = (float)kept / (float)T_TOKENS;
            float pi = g_pi_sum[k] / (float)T_TOKENS;
            aux += fi * pi;
        }
        g_aux = aux * (float)N_EXPERTS;
        g_dropped = drop;
    }
}

__global__ void rank_kernel() {
    __shared__ int warpCnt[32][N_EXPERTS];
    __shared__ int warpOff[32][N_EXPERTS];
    int tid = threadIdx.x, w = tid >> 5, lane = tid & 31;
    int t = blockIdx.x * 1024 + tid;
    int e = g_expert[t];
    unsigned lt = (lane == 0) ? 0u : (0xffffffffu >> (32 - lane));
    int myrank = 0;
#pragma unroll
    for (int k = 0; k < N_EXPERTS; k++) {
        unsigned m = __ballot_sync(0xffffffffu, e == k);
        if (lane == 0) warpCnt[w][k] = __popc(m);
        if (e == k) myrank = __popc(m & lt);
    }
    __syncthreads();
    if (tid < 32 * N_EXPERTS) {
        int ww = tid >> 3, k = tid & 7;
        int s = 0;
        for (int u = 0; u < ww; u++) s += warpCnt[u][k];
        warpOff[ww][k] = s;
    }
    __syncthreads();
    int pos = g_blockOffsets[blockIdx.x * N_EXPERTS + e] + warpOff[w][e] + myrank;
    g_pos[t] = pos;
    if (pos < CAPACITY) g_slot2tok[e * CAPACITY + pos] = t;
}

// ---------------- tf32 mma.sync GEMM, BK=32, 3-stage ring ----------------
template<int K_TOT, bool GATHER, bool RELU>
__global__ void __launch_bounds__(512, 1)
gemm_mma(float* __restrict__ Dglob) {
    extern __shared__ float smem[];
    float* sA = smem;
    float* sB = smem + 3 * STAGE_F;
    int* tokS = (int*)(smem + 6 * STAGE_F);

    int e = blockIdx.z;
    int ne = g_total[e]; if (ne > CAPACITY) ne = CAPACITY;
    int m0 = blockIdx.y * 128;
    if (m0 >= ne) return;
    int n0 = blockIdx.x * 128;

    int tid = threadIdx.x;
    int wid = tid >> 5, lane = tid & 31;
    int wm = wid >> 2, wn = wid & 3;
    int qr = lane >> 2, j = lane & 3;

    if (GATHER && tid < 128) {
        int m = m0 + tid;
        tokS[tid] = (m < ne) ? g_slot2tok[e * CAPACITY + m] : 0;
    }
    __syncthreads();

    const float* Bbase = (RELU ? g_Wit : g_Wot) +
        ((size_t)e * (RELU ? D_FF : D_MODEL) + n0) * K_TOT;
    const float* Hbase = g_H + ((size_t)e * CAPACITY + m0) * (size_t)D_FF;

    int lrow = tid >> 2, lq = tid & 3;
    const float* aRowPtr;
    if (GATHER) aRowPtr = g_xt + (size_t)tokS[lrow] * D_MODEL + lq * 4;
    else        aRowPtr = Hbase + (size_t)lrow * D_FF + lq * 4;
    const float* bRowPtr = Bbase + (size_t)lrow * K_TOT + lq * 4;
    uint32_t sAu = s2u(sA) + (lrow * LDS_F + lq * 4) * 4;
    uint32_t sBu = s2u(sB) + (lrow * LDS_F + lq * 4) * 4;

    float acc[2][4][4];
#pragma unroll
    for (int mi = 0; mi < 2; mi++)
#pragma unroll
        for (int ni = 0; ni < 4; ni++)
#pragma unroll
            for (int r = 0; r < 4; r++) acc[mi][ni][r] = 0.f;

    const int NS = K_TOT / BK;
    // prologue: stages 0,1 in flight (each = 2 float4 per operand per thread)
#pragma unroll
    for (int s = 0; s < 2; s++) {
        uint32_t so = s * STAGE_B4;
        cpasync16(sAu + so,      aRowPtr + s * BK);
        cpasync16(sAu + so + 64, aRowPtr + s * BK + 16);
        cpasync16(sBu + so,      bRowPtr + s * BK);
        cpasync16(sBu + so + 64, bRowPtr + s * BK + 16);
        asm volatile("cp.async.commit_group;" ::: "memory");
    }

    int cur = 0, pre = 2;   // buffer indices: s%3 and (s+2)%3
    for (int s = 0; s < NS; s++) {
        asm volatile("cp.async.wait_group 1;" ::: "memory");
        __syncthreads();
        if (s + 2 < NS) {
            uint32_t so = pre * STAGE_B4;
            const float* ap = aRowPtr + (s + 2) * BK;
            const float* bp = bRowPtr + (s + 2) * BK;
            cpasync16(sAu + so,      ap);
            cpasync16(sAu + so + 64, ap + 16);
            cpasync16(sBu + so,      bp);
            cpasync16(sBu + so + 64, bp + 16);
        }
        asm volatile("cp.async.commit_group;" ::: "memory");

        const float* A = sA + cur * STAGE_F;
        const float* B = sB + cur * STAGE_F;

        // process 4 kf-groups in 2 register-friendly chunks
#pragma unroll
        for (int kfc = 0; kfc < 2; kfc++) {
            uint2 af[2][2][2];   // [kf][mi][rowhalf]
            uint2 bf[2][4];
#pragma unroll
            for (int kf = 0; kf < 2; kf++) {
                int co = (kfc * 2 + kf) * 8 + 2 * j;
#pragma unroll
                for (int mi = 0; mi < 2; mi++) {
                    int r = wm * 32 + mi * 16 + qr;
                    af[kf][mi][0] = *(const uint2*)&A[r * LDS_F + co];
                    af[kf][mi][1] = *(const uint2*)&A[(r + 8) * LDS_F + co];
                }
#pragma unroll
                for (int ni = 0; ni < 4; ni++) {
                    int r = wn * 32 + ni * 8 + qr;
                    bf[kf][ni] = *(const uint2*)&B[r * LDS_F + co];
                }
            }
#pragma unroll
            for (int kf = 0; kf < 2; kf++)
#pragma unroll
                for (int mi = 0; mi < 2; mi++)
#pragma unroll
                    for (int ni = 0; ni < 4; ni++)
                        mma8(acc[mi][ni],
                             af[kf][mi][0].x, af[kf][mi][1].x,
                             af[kf][mi][0].y, af[kf][mi][1].y,
                             bf[kf][ni].x, bf[kf][ni].y);
        }
        cur++; if (cur == 3) cur = 0;
        pre++; if (pre == 3) pre = 0;
    }

    // epilogue
    int j2 = 2 * j;
    int p0 = ((j2 & 3) << 1) | (j2 >> 2);
    int p1 = (((j2 + 1) & 3) << 1) | ((j2 + 1) >> 2);
#pragma unroll
    for (int mi = 0; mi < 2; mi++) {
#pragma unroll
        for (int half = 0; half < 2; half++) {
            int m = m0 + wm * 32 + mi * 16 + qr + half * 8;
            bool valid = m < ne;
            float sc = 1.f;
            float* rowptr;
            if (RELU) {
                rowptr = g_H + ((size_t)e * CAPACITY + m) * D_FF + n0;
            } else {
                int tk = valid ? g_slot2tok[e * CAPACITY + m] : 0;
                sc = g_top1[tk];
                rowptr = Dglob + (size_t)tk * D_MODEL + n0;
            }
            if (valid) {
#pragma unroll
                for (int ni = 0; ni < 4; ni++) {
                    float v0 = acc[mi][ni][half * 2 + 0];
                    float v1 = acc[mi][ni][half * 2 + 1];
                    if (RELU) {
                        int cb = wn * 32 + ni * 8;
                        rowptr[cb + p0] = tf32r(fmaxf(v0, 0.f));
                        rowptr[cb + p1] = tf32r(fmaxf(v1, 0.f));
                    } else {
                        int c = wn * 32 + ni * 8 + j2;
                        float2 v; v.x = v0 * sc; v.y = v1 * sc;
                        *(float2*)(rowptr + c) = v;
                    }
                }
            }
        }
    }
}

__global__ void drop_kernel(float* __restrict__ outp) {
    for (int t = blockIdx.x * blockDim.x + threadIdx.x; t < T_TOKENS;
         t += gridDim.x * blockDim.x) {
        if (g_pos[t] >= CAPACITY) {
            float4 z = make_float4(0.f, 0.f, 0.f, 0.f);
            float4* p = (float4*)(outp + (size_t)t * D_MODEL);
            for (int i = 0; i < D_MODEL / 4; i++) p[i] = z;
        }
    }
}

__global__ void extras_kernel(float* __restrict__ outp, long long out_size) {
    long long i = (long long)blockIdx.x * blockDim.x + threadIdx.x;
    long long off = OUT_ELEMS + i;
    if (off >= out_size) return;
    long long r = i;
    if (r < ONEHOT_E) {
        int t = (int)(r >> 3), e = (int)(r & 7);
        outp[off] = (g_expert[t] == e && g_pos[t] < CAPACITY) ? 1.f : 0.f;
        return;
    }
    r -= ONEHOT_E;
    if (r < T_TOKENS) { outp[off] = g_top1[r]; return; }
    r -= T_TOKENS;
    if (r < PROBS_E) { outp[off] = g_probs[r]; return; }
    r -= PROBS_E;
    if (r == 0) { outp[off] = g_aux; return; }
    outp[off] = (float)g_dropped;
}

// ---------------- launch ----------------
extern "C" void kernel_launch(void* const* d_in, const int* in_sizes, int n_in,
                              void* d_out, int out_size) {
    const float* x  = (const float*)d_in[0];
    const float* Wr = (const float*)d_in[1];
    const float* br = (const float*)d_in[2];
    const float* Wi = (const float*)d_in[3];
    const float* Wo = (const float*)d_in[4];
    float* outp = (float*)d_out;

    cudaFuncSetAttribute(gemm_mma<D_MODEL, true, true>,
                         cudaFuncAttributeMaxDynamicSharedMemorySize, SMEM_GEMM);
    cudaFuncSetAttribute(gemm_mma<D_FF, false, false>,
                         cudaFuncAttributeMaxDynamicSharedMemorySize, SMEM_GEMM);

    zero_kernel<<<1, 32>>>();
    router_kernel<<<T_TOKENS / 8, 256>>>(x, Wr, br);
    count_kernel<<<NB, 1024>>>();
    scan_kernel<<<1, 32>>>();
    rank_kernel<<<NB, 1024>>>();

    round_perm_kernel<0><<<(unsigned)((T_TOKENS * (long long)D_MODEL / 4) / 256), 256>>>((const float4*)x);
    round_perm_kernel<1><<<(unsigned)(((long long)N_EXPERTS * D_FF * D_MODEL / 4) / 256), 256>>>((const float4*)Wi);
    round_perm_kernel<2><<<(unsigned)(((long long)N_EXPERTS * D_MODEL * D_FF / 4) / 256), 256>>>((const float4*)Wo);

    dim3 g1(D_FF / 128, CAPACITY / 128, N_EXPERTS);
    gemm_mma<D_MODEL, true, true><<<g1, 512, SMEM_GEMM>>>(nullptr);
    dim3 g2(D_MODEL / 128, CAPACITY / 128, N_EXPERTS);
    gemm_mma<D_FF, false, false><<<g2, 512, SMEM_GEMM>>>(outp);

    drop_kernel<<<256, 256>>>(outp);

    long long extra = (long long)out_size - OUT_ELEMS;
    if (extra > 0) {
        unsigned nb = (unsigned)((extra + 255) / 256);
        extras_kernel<<<nb, 256>>>(outp, (long long)out_size);
    }
}

// round 9
// speedup vs baseline: 4.3973x; 1.6149x over previous
#include <cuda_runtime.h>
#include <cuda_fp16.h>
#include <math.h>
#include <stdint.h>

#define D_MODEL   512
#define D_FF      2048
#define N_EXPERTS 8
#define CAPACITY  10240
#define T_TOKENS  65536
#define NB        64

#define OUT_ELEMS   ((long long)T_TOKENS * D_MODEL)
#define ONEHOT_E    ((long long)T_TOKENS * N_EXPERTS)
#define PROBS_E     ((long long)T_TOKENS * N_EXPERTS)

// fp16 GEMM smem: 3-stage ring, 128 rows x 80 halves (64 data + 16 pad).
// LDS.64 banks: (40*qr + 8*kc + 2j) distinct per 16-lane phase (qr 0..3 -> +0/8/16/24).
#define BK        64                     // k elements per stage
#define LDS_H     80                     // halves per smem row
#define STAGE_H   (128 * LDS_H)          // 10240 halves
#define STAGE_B2  (STAGE_H * 2)          // 20480 bytes
#define SMEM_GEMM (6 * STAGE_B2 + 512 + 128)

// ---------------- scratch ----------------
__device__ float g_probs[T_TOKENS * N_EXPERTS];
__device__ float g_top1[T_TOKENS];
__device__ int   g_expert[T_TOKENS];
__device__ int   g_pos[T_TOKENS];
__device__ int   g_blockCounts[NB * N_EXPERTS];
__device__ int   g_blockOffsets[NB * N_EXPERTS];
__device__ int   g_total[N_EXPERTS];
__device__ float g_pi_sum[N_EXPERTS];
__device__ float g_aux;
__device__ int   g_dropped;
__device__ int   g_slot2tok[N_EXPERTS * CAPACITY];
// fp16, k-permuted within 16-groups: p(k) = 4*((k&7)>>1) + (k&1) + 2*(k>>3)
__device__ __half g_xh[(size_t)T_TOKENS * D_MODEL];
__device__ __half g_Wih[(size_t)N_EXPERTS * D_FF * D_MODEL];
__device__ __half g_Woh[(size_t)N_EXPERTS * D_MODEL * D_FF];
__device__ __half g_Hh[(size_t)N_EXPERTS * CAPACITY * D_FF];

// ---------------- helpers ----------------
__device__ __forceinline__ uint32_t s2u(const void* p) {
    uint32_t a;
    asm("{ .reg .u64 t; cvta.to.shared.u64 t, %1; cvt.u32.u64 %0, t; }" : "=r"(a) : "l"(p));
    return a;
}
__device__ __forceinline__ void cpasync16(uint32_t saddr, const void* gaddr) {
    asm volatile("cp.async.cg.shared.global [%0], [%1], 16;" :: "r"(saddr), "l"(gaddr) : "memory");
}
__device__ __forceinline__ void mma16(float* c, uint32_t a0, uint32_t a1, uint32_t a2,
                                      uint32_t a3, uint32_t b0, uint32_t b1) {
    asm volatile(
        "mma.sync.aligned.m16n8k16.row.col.f32.f16.f16.f32 "
        "{%0,%1,%2,%3}, {%4,%5,%6,%7}, {%8,%9}, {%0,%1,%2,%3};"
        : "+f"(c[0]), "+f"(c[1]), "+f"(c[2]), "+f"(c[3])
        : "r"(a0), "r"(a1), "r"(a2), "r"(a3), "r"(b0), "r"(b1));
}
__device__ __forceinline__ int permk16(int k) {
    return 4 * ((k & 7) >> 1) + (k & 1) + 2 * (k >> 3);
}

// ---------------- pre-round + permute to fp16 (once per call) ----------------
// One thread per 16-float group.
template<int WHICH>
__global__ void cvt_perm_kernel(const float* __restrict__ s) {
    long long g = (long long)blockIdx.x * 256 + threadIdx.x;
    long long base = g * 16;
    __half out[16];
#pragma unroll
    for (int q = 0; q < 4; q++) {
        float4 v = *(const float4*)(s + base + q * 4);
        float vals[4] = {v.x, v.y, v.z, v.w};
#pragma unroll
        for (int u = 0; u < 4; u++) {
            int k = q * 4 + u;
            out[permk16(k)] = __float2half_rn(vals[u]);
        }
    }
    __half* dst = (WHICH == 0) ? g_xh : (WHICH == 1) ? g_Wih : g_Woh;
    *(uint4*)(dst + base) = *(uint4*)out;
    *(uint4*)(dst + base + 8) = *(uint4*)(out + 8);
}

// ---------------- routing (known-correct from R1) ----------------
__global__ void zero_kernel() {
    int i = threadIdx.x;
    if (i < N_EXPERTS) g_pi_sum[i] = 0.f;
}

__global__ void router_kernel(const float* __restrict__ x,
                              const float* __restrict__ Wr,
                              const float* __restrict__ br) {
    __shared__ float Ws[N_EXPERTS * D_MODEL];
    __shared__ float brs[N_EXPERTS];
    __shared__ float pis[N_EXPERTS];
    int tid = threadIdx.x;
    for (int i = tid; i < N_EXPERTS * D_MODEL; i += 256) Ws[i] = Wr[i];
    if (tid < N_EXPERTS) { brs[tid] = br[tid]; pis[tid] = 0.f; }
    __syncthreads();

    int warp = tid >> 5, lane = tid & 31;
    int t = blockIdx.x * 8 + warp;

    float acc[N_EXPERTS];
#pragma unroll
    for (int e = 0; e < N_EXPERTS; e++) acc[e] = 0.f;
    const float* xr = x + (size_t)t * D_MODEL;
#pragma unroll
    for (int i = 0; i < D_MODEL / 32; i++) {
        int c = lane + i * 32;
        float v = xr[c];
#pragma unroll
        for (int e = 0; e < N_EXPERTS; e++) acc[e] += v * Ws[e * D_MODEL + c];
    }
#pragma unroll
    for (int e = 0; e < N_EXPERTS; e++) {
#pragma unroll
        for (int off = 16; off > 0; off >>= 1)
            acc[e] += __shfl_down_sync(0xffffffffu, acc[e], off);
    }
    if (lane == 0) {
        float l[N_EXPERTS];
        float mx = -INFINITY; int idx = 0;
#pragma unroll
        for (int e = 0; e < N_EXPERTS; e++) {
            l[e] = acc[e] + brs[e];
            if (l[e] > mx) { mx = l[e]; idx = e; }
        }
        float s = 0.f, pr[N_EXPERTS];
#pragma unroll
        for (int e = 0; e < N_EXPERTS; e++) { pr[e] = expf(l[e] - mx); s += pr[e]; }
        float inv = 1.f / s;
#pragma unroll
        for (int e = 0; e < N_EXPERTS; e++) {
            float p = pr[e] * inv;
            g_probs[(size_t)t * N_EXPERTS + e] = p;
            atomicAdd(&pis[e], p);
        }
        g_top1[t] = pr[idx] * inv;
        g_expert[t] = idx;
    }
    __syncthreads();
    if (tid < N_EXPERTS) atomicAdd(&g_pi_sum[tid], pis[tid]);
}

__global__ void count_kernel() {
    __shared__ int c[N_EXPERTS];
    if (threadIdx.x < N_EXPERTS) c[threadIdx.x] = 0;
    __syncthreads();
    int t = blockIdx.x * 1024 + threadIdx.x;
    atomicAdd(&c[g_expert[t]], 1);
    __syncthreads();
    if (threadIdx.x < N_EXPERTS)
        g_blockCounts[blockIdx.x * N_EXPERTS + threadIdx.x] = c[threadIdx.x];
}

__global__ void scan_kernel() {
    int e = threadIdx.x;
    if (e < N_EXPERTS) {
        int run = 0;
        for (int b = 0; b < NB; b++) {
            g_blockOffsets[b * N_EXPERTS + e] = run;
            run += g_blockCounts[b * N_EXPERTS + e];
        }
        g_total[e] = run;
    }
    __syncthreads();
    if (e == 0) {
        float aux = 0.f; int drop = 0;
        for (int k = 0; k < N_EXPERTS; k++) {
            int tot = g_total[k];
            int kept = tot < CAPACITY ? tot : CAPACITY;
            drop += tot - kept;
            float fi = (float)kept / (float)T_TOKENS;
            float pi = g_pi_sum[k] / (float)T_TOKENS;
            aux += fi * pi;
        }
        g_aux = aux * (float)N_EXPERTS;
        g_dropped = drop;
    }
}

__global__ void rank_kernel() {
    __shared__ int warpCnt[32][N_EXPERTS];
    __shared__ int warpOff[32][N_EXPERTS];
    int tid = threadIdx.x, w = tid >> 5, lane = tid & 31;
    int t = blockIdx.x * 1024 + tid;
    int e = g_expert[t];
    unsigned lt = (lane == 0) ? 0u : (0xffffffffu >> (32 - lane));
    int myrank = 0;
#pragma unroll
    for (int k = 0; k < N_EXPERTS; k++) {
        unsigned m = __ballot_sync(0xffffffffu, e == k);
        if (lane == 0) warpCnt[w][k] = __popc(m);
        if (e == k) myrank = __popc(m & lt);
    }
    __syncthreads();
    if (tid < 32 * N_EXPERTS) {
        int ww = tid >> 3, k = tid & 7;
        int s = 0;
        for (int u = 0; u < ww; u++) s += warpCnt[u][k];
        warpOff[ww][k] = s;
    }
    __syncthreads();
    int pos = g_blockOffsets[blockIdx.x * N_EXPERTS + e] + warpOff[w][e] + myrank;
    g_pos[t] = pos;
    if (pos < CAPACITY) g_slot2tok[e * CAPACITY + pos] = t;
}

// ---------------- fp16 mma.sync GEMM, BK=64, 3-stage ring ----------------
template<int K_TOT, bool GATHER, bool RELU>
__global__ void __launch_bounds__(512, 1)
gemm_mma(float* __restrict__ Dglob) {
    extern __shared__ __half smemh[];
    __half* sA = smemh;
    __half* sB = smemh + 3 * STAGE_H;
    int* tokS = (int*)(smemh + 6 * STAGE_H);

    int e = blockIdx.z;
    int ne = g_total[e]; if (ne > CAPACITY) ne = CAPACITY;
    int m0 = blockIdx.y * 128;
    if (m0 >= ne) return;
    int n0 = blockIdx.x * 128;

    int tid = threadIdx.x;
    int wid = tid >> 5, lane = tid & 31;
    int wm = wid >> 2, wn = wid & 3;
    int qr = lane >> 2, j = lane & 3;

    if (GATHER && tid < 128) {
        int m = m0 + tid;
        tokS[tid] = (m < ne) ? g_slot2tok[e * CAPACITY + m] : 0;
    }
    __syncthreads();

    const __half* Bbase = (RELU ? g_Wih : g_Woh) +
        ((size_t)e * (RELU ? D_FF : D_MODEL) + n0) * K_TOT;
    const __half* Hbase = g_Hh + ((size_t)e * CAPACITY + m0) * (size_t)D_FF;

    int lrow = tid >> 2, lq = tid & 3;     // 4 threads/row, 32B each
    const __half* aRowPtr;
    if (GATHER) aRowPtr = g_xh + (size_t)tokS[lrow] * D_MODEL + lq * 16;
    else        aRowPtr = Hbase + (size_t)lrow * D_FF + lq * 16;
    const __half* bRowPtr = Bbase + (size_t)lrow * K_TOT + lq * 16;
    uint32_t sAu = s2u(sA) + (lrow * LDS_H + lq * 16) * 2;
    uint32_t sBu = s2u(sB) + (lrow * LDS_H + lq * 16) * 2;

    float acc[2][4][4];
#pragma unroll
    for (int mi = 0; mi < 2; mi++)
#pragma unroll
        for (int ni = 0; ni < 4; ni++)
#pragma unroll
            for (int r = 0; r < 4; r++) acc[mi][ni][r] = 0.f;

    const int NS = K_TOT / BK;
    // prologue: stages 0,1
#pragma unroll
    for (int s = 0; s < 2; s++) {
        uint32_t so = s * STAGE_B2;
        cpasync16(sAu + so,      aRowPtr + s * BK);
        cpasync16(sAu + so + 16, aRowPtr + s * BK + 8);
        cpasync16(sBu + so,      bRowPtr + s * BK);
        cpasync16(sBu + so + 16, bRowPtr + s * BK + 8);
        asm volatile("cp.async.commit_group;" ::: "memory");
    }

    int cur = 0, pre = 2;
    for (int s = 0; s < NS; s++) {
        asm volatile("cp.async.wait_group 1;" ::: "memory");
        __syncthreads();
        if (s + 2 < NS) {
            uint32_t so = pre * STAGE_B2;
            const __half* ap = aRowPtr + (s + 2) * BK;
            const __half* bp = bRowPtr + (s + 2) * BK;
            cpasync16(sAu + so,      ap);
            cpasync16(sAu + so + 16, ap + 8);
            cpasync16(sBu + so,      bp);
            cpasync16(sBu + so + 16, bp + 8);
        }
        asm volatile("cp.async.commit_group;" ::: "memory");

        const __half* A = sA + cur * STAGE_H;
        const __half* B = sB + cur * STAGE_H;

#pragma unroll
        for (int kc = 0; kc < 4; kc++) {       // 4 x k16 per stage
            int co = kc * 16 + j * 4;          // halves offset (permuted layout)
            uint2 af[2][2], bf[4];
#pragma unroll
            for (int mi = 0; mi < 2; mi++) {
                int r = wm * 32 + mi * 16 + qr;
                af[mi][0] = *(const uint2*)&A[r * LDS_H + co];
                af[mi][1] = *(const uint2*)&A[(r + 8) * LDS_H + co];
            }
#pragma unroll
            for (int ni = 0; ni < 4; ni++) {
                int r = wn * 32 + ni * 8 + qr;
                bf[ni] = *(const uint2*)&B[r * LDS_H + co];
            }
#pragma unroll
            for (int mi = 0; mi < 2; mi++)
#pragma unroll
                for (int ni = 0; ni < 4; ni++)
                    mma16(acc[mi][ni],
                          af[mi][0].x, af[mi][1].x, af[mi][0].y, af[mi][1].y,
                          bf[ni].x, bf[ni].y);
        }
        cur++; if (cur == 3) cur = 0;
        pre++; if (pre == 3) pre = 0;
    }

    // epilogue
#pragma unroll
    for (int mi = 0; mi < 2; mi++) {
#pragma unroll
        for (int half = 0; half < 2; half++) {
            int m = m0 + wm * 32 + mi * 16 + qr + half * 8;
            bool valid = m < ne;
            if (!valid) continue;
            if (RELU) {
                __half* rowptr = g_Hh + ((size_t)e * CAPACITY + m) * D_FF + n0;
#pragma unroll
                for (int ni = 0; ni < 4; ni++) {
                    float v0 = fmaxf(acc[mi][ni][half * 2 + 0], 0.f);
                    float v1 = fmaxf(acc[mi][ni][half * 2 + 1], 0.f);
                    int c = wn * 32 + ni * 8 + 2 * j;
                    int base16 = c & ~15;
                    int cm = c & 15;
                    int off = 4 * ((cm & 7) >> 1) + 2 * (cm >> 3);  // even pos
                    __half2 hv = __floats2half2_rn(v0, v1);
                    *(__half2*)(rowptr + base16 + off) = hv;
                }
            } else {
                int tk = g_slot2tok[e * CAPACITY + m];
                float sc = g_top1[tk];
                float* rowptr = Dglob + (size_t)tk * D_MODEL + n0;
#pragma unroll
                for (int ni = 0; ni < 4; ni++) {
                    int c = wn * 32 + ni * 8 + 2 * j;
                    float2 v;
                    v.x = acc[mi][ni][half * 2 + 0] * sc;
                    v.y = acc[mi][ni][half * 2 + 1] * sc;
                    *(float2*)(rowptr + c) = v;
                }
            }
        }
    }
}

__global__ void drop_kernel(float* __restrict__ outp) {
    for (int t = blockIdx.x * blockDim.x + threadIdx.x; t < T_TOKENS;
         t += gridDim.x * blockDim.x) {
        if (g_pos[t] >= CAPACITY) {
            float4 z = make_float4(0.f, 0.f, 0.f, 0.f);
            float4* p = (float4*)(outp + (size_t)t * D_MODEL);
            for (int i = 0; i < D_MODEL / 4; i++) p[i] = z;
        }
    }
}

__global__ void extras_kernel(float* __restrict__ outp, long long out_size) {
    long long i = (long long)blockIdx.x * blockDim.x + threadIdx.x;
    long long off = OUT_ELEMS + i;
    if (off >= out_size) return;
    long long r = i;
    if (r < ONEHOT_E) {
        int t = (int)(r >> 3), e = (int)(r & 7);
        outp[off] = (g_expert[t] == e && g_pos[t] < CAPACITY) ? 1.f : 0.f;
        return;
    }
    r -= ONEHOT_E;
    if (r < T_TOKENS) { outp[off] = g_top1[r]; return; }
    r -= T_TOKENS;
    if (r < PROBS_E) { outp[off] = g_probs[r]; return; }
    r -= PROBS_E;
    if (r == 0) { outp[off] = g_aux; return; }
    outp[off] = (float)g_dropped;
}

// ---------------- launch ----------------
extern "C" void kernel_launch(void* const* d_in, const int* in_sizes, int n_in,
                              void* d_out, int out_size) {
    const float* x  = (const float*)d_in[0];
    const float* Wr = (const float*)d_in[1];
    const float* br = (const float*)d_in[2];
    const float* Wi = (const float*)d_in[3];
    const float* Wo = (const float*)d_in[4];
    float* outp = (float*)d_out;

    cudaFuncSetAttribute(gemm_mma<D_MODEL, true, true>,
                         cudaFuncAttributeMaxDynamicSharedMemorySize, SMEM_GEMM);
    cudaFuncSetAttribute(gemm_mma<D_FF, false, false>,
                         cudaFuncAttributeMaxDynamicSharedMemorySize, SMEM_GEMM);

    zero_kernel<<<1, 32>>>();
    router_kernel<<<T_TOKENS / 8, 256>>>(x, Wr, br);
    count_kernel<<<NB, 1024>>>();
    scan_kernel<<<1, 32>>>();
    rank_kernel<<<NB, 1024>>>();

    cvt_perm_kernel<0><<<(unsigned)((T_TOKENS * (long long)D_MODEL / 16) / 256), 256>>>(x);
    cvt_perm_kernel<1><<<(unsigned)(((long long)N_EXPERTS * D_FF * D_MODEL / 16) / 256), 256>>>(Wi);
    cvt_perm_kernel<2><<<(unsigned)(((long long)N_EXPERTS * D_MODEL * D_FF / 16) / 256), 256>>>(Wo);

    dim3 g1(D_FF / 128, CAPACITY / 128, N_EXPERTS);
    gemm_mma<D_MODEL, true, true><<<g1, 512, SMEM_GEMM>>>(nullptr);
    dim3 g2(D_MODEL / 128, CAPACITY / 128, N_EXPERTS);
    gemm_mma<D_FF, false, false><<<g2, 512, SMEM_GEMM>>>(outp);

    drop_kernel<<<256, 256>>>(outp);

    long long extra = (long long)out_size - OUT_ELEMS;
    if (extra > 0) {
        unsigned nb = (unsigned)((extra + 255) / 256);
        extras_kernel<<<nb, 256>>>(outp, (long long)out_size);
    }
}

// round 10
// speedup vs baseline: 4.4807x; 1.0190x over previous
#include <cuda_runtime.h>
#include <cuda_fp16.h>
#include <math.h>
#include <stdint.h>

#define D_MODEL   512
#define D_FF      2048
#define N_EXPERTS 8
#define CAPACITY  10240
#define T_TOKENS  65536
#define NB        64

#define OUT_ELEMS   ((long long)T_TOKENS * D_MODEL)
#define ONEHOT_E    ((long long)T_TOKENS * N_EXPERTS)
#define PROBS_E     ((long long)T_TOKENS * N_EXPERTS)

// fp16 GEMM smem: 4-stage ring, 128 rows x 80 halves (64 data + 16 pad).
#define BK        64
#define LDS_H     80
#define STAGE_H   (128 * LDS_H)          // 10240 halves
#define STAGE_B2  (STAGE_H * 2)          // 20480 bytes
#define NSTAGE    4
#define SMEM_GEMM (2 * NSTAGE * STAGE_B2 + 512 + 128)   // 164 KB

// ---------------- scratch ----------------
__device__ float g_probs[T_TOKENS * N_EXPERTS];
__device__ float g_top1[T_TOKENS];
__device__ int   g_expert[T_TOKENS];
__device__ int   g_pos[T_TOKENS];
__device__ int   g_blockCounts[NB * N_EXPERTS];
__device__ int   g_blockOffsets[NB * N_EXPERTS];
__device__ int   g_total[N_EXPERTS];
__device__ float g_pi_sum[N_EXPERTS];
__device__ float g_aux;
__device__ int   g_dropped;
__device__ int   g_slot2tok[N_EXPERTS * CAPACITY];
// fp16, k-permuted within 16-groups: p(k) = 4*((k&7)>>1) + (k&1) + 2*(k>>3)
__device__ __half g_xh[(size_t)T_TOKENS * D_MODEL];
__device__ __half g_Wih[(size_t)N_EXPERTS * D_FF * D_MODEL];
__device__ __half g_Woh[(size_t)N_EXPERTS * D_MODEL * D_FF];
__device__ __half g_Hh[(size_t)N_EXPERTS * CAPACITY * D_FF];

// ---------------- helpers ----------------
__device__ __forceinline__ uint32_t s2u(const void* p) {
    uint32_t a;
    asm("{ .reg .u64 t; cvta.to.shared.u64 t, %1; cvt.u32.u64 %0, t; }" : "=r"(a) : "l"(p));
    return a;
}
__device__ __forceinline__ void cpasync16(uint32_t saddr, const void* gaddr) {
    asm volatile("cp.async.cg.shared.global [%0], [%1], 16;" :: "r"(saddr), "l"(gaddr) : "memory");
}
__device__ __forceinline__ void mma16(float* c, uint32_t a0, uint32_t a1, uint32_t a2,
                                      uint32_t a3, uint32_t b0, uint32_t b1) {
    asm volatile(
        "mma.sync.aligned.m16n8k16.row.col.f32.f16.f16.f32 "
        "{%0,%1,%2,%3}, {%4,%5,%6,%7}, {%8,%9}, {%0,%1,%2,%3};"
        : "+f"(c[0]), "+f"(c[1]), "+f"(c[2]), "+f"(c[3])
        : "r"(a0), "r"(a1), "r"(a2), "r"(a3), "r"(b0), "r"(b1));
}
__device__ __forceinline__ int permk16(int k) {
    return 4 * ((k & 7) >> 1) + (k & 1) + 2 * (k >> 3);
}

// ---------------- weight cvt+permute to fp16 (once per call) ----------------
template<int WHICH>
__global__ void cvt_perm_kernel(const float* __restrict__ s) {
    long long g = (long long)blockIdx.x * 256 + threadIdx.x;
    long long base = g * 16;
    __half out[16];
#pragma unroll
    for (int q = 0; q < 4; q++) {
        float4 v = *(const float4*)(s + base + q * 4);
        float vals[4] = {v.x, v.y, v.z, v.w};
#pragma unroll
        for (int u = 0; u < 4; u++) {
            int k = q * 4 + u;
            out[permk16(k)] = __float2half_rn(vals[u]);
        }
    }
    __half* dst = (WHICH == 1) ? g_Wih : g_Woh;
    *(uint4*)(dst + base) = *(uint4*)out;
    *(uint4*)(dst + base + 8) = *(uint4*)(out + 8);
}

// ---------------- routing ----------------
__global__ void zero_kernel() {
    int i = threadIdx.x;
    if (i < N_EXPERTS) g_pi_sum[i] = 0.f;
}

// One warp per token; fused: router + x->fp16 permuted conversion (L1-hot).
__global__ void router_kernel(const float* __restrict__ x,
                              const float* __restrict__ Wr,
                              const float* __restrict__ br) {
    __shared__ float Ws[N_EXPERTS * D_MODEL];
    __shared__ float brs[N_EXPERTS];
    __shared__ float pis[N_EXPERTS];
    int tid = threadIdx.x;
    for (int i = tid; i < N_EXPERTS * D_MODEL; i += 256) Ws[i] = Wr[i];
    if (tid < N_EXPERTS) { brs[tid] = br[tid]; pis[tid] = 0.f; }
    __syncthreads();

    int warp = tid >> 5, lane = tid & 31;
    int t = blockIdx.x * 8 + warp;

    float acc[N_EXPERTS];
#pragma unroll
    for (int e = 0; e < N_EXPERTS; e++) acc[e] = 0.f;
    const float* xr = x + (size_t)t * D_MODEL;
#pragma unroll
    for (int i = 0; i < D_MODEL / 32; i++) {
        int c = lane + i * 32;
        float v = xr[c];
#pragma unroll
        for (int e = 0; e < N_EXPERTS; e++) acc[e] += v * Ws[e * D_MODEL + c];
    }

    // fused fp16 convert + k16-permute (re-read is L1-hot; stores coalesced)
    {
        __half out[16];
        const float4* xq = (const float4*)xr + lane * 4;
#pragma unroll
        for (int q = 0; q < 4; q++) {
            float4 v = xq[q];
            float vals[4] = {v.x, v.y, v.z, v.w};
#pragma unroll
            for (int u = 0; u < 4; u++) {
                int k = q * 4 + u;
                out[permk16(k)] = __float2half_rn(vals[u]);
            }
        }
        uint4* dst = (uint4*)(g_xh + (size_t)t * D_MODEL + lane * 16);
        dst[0] = *(uint4*)out;
        dst[1] = *(uint4*)(out + 8);
    }

#pragma unroll
    for (int e = 0; e < N_EXPERTS; e++) {
#pragma unroll
        for (int off = 16; off > 0; off >>= 1)
            acc[e] += __shfl_down_sync(0xffffffffu, acc[e], off);
    }
    if (lane == 0) {
        float l[N_EXPERTS];
        float mx = -INFINITY; int idx = 0;
#pragma unroll
        for (int e = 0; e < N_EXPERTS; e++) {
            l[e] = acc[e] + brs[e];
            if (l[e] > mx) { mx = l[e]; idx = e; }
        }
        float s = 0.f, pr[N_EXPERTS];
#pragma unroll
        for (int e = 0; e < N_EXPERTS; e++) { pr[e] = expf(l[e] - mx); s += pr[e]; }
        float inv = 1.f / s;
#pragma unroll
        for (int e = 0; e < N_EXPERTS; e++) {
            float p = pr[e] * inv;
            g_probs[(size_t)t * N_EXPERTS + e] = p;
            atomicAdd(&pis[e], p);
        }
        g_top1[t] = pr[idx] * inv;
        g_expert[t] = idx;
    }
    __syncthreads();
    if (tid < N_EXPERTS) atomicAdd(&g_pi_sum[tid], pis[tid]);
}

__global__ void count_kernel() {
    __shared__ int c[N_EXPERTS];
    if (threadIdx.x < N_EXPERTS) c[threadIdx.x] = 0;
    __syncthreads();
    int t = blockIdx.x * 1024 + threadIdx.x;
    atomicAdd(&c[g_expert[t]], 1);
    __syncthreads();
    if (threadIdx.x < N_EXPERTS)
        g_blockCounts[blockIdx.x * N_EXPERTS + threadIdx.x] = c[threadIdx.x];
}

// Parallel scan: 512 threads; tid = e*64 + b; warp pairs per expert.
__global__ void scan_kernel() {
    __shared__ int warpTot[16];
    __shared__ int tot[N_EXPERTS];
    int tid = threadIdx.x;
    int e = tid >> 6, b = tid & 63;
    int w = tid >> 5, lane = tid & 31;
    int v = g_blockCounts[b * N_EXPERTS + e];
    int incl = v;
#pragma unroll
    for (int off = 1; off < 32; off <<= 1) {
        int n = __shfl_up_sync(0xffffffffu, incl, off);
        if (lane >= off) incl += n;
    }
    if (lane == 31) warpTot[w] = incl;
    __syncthreads();
    if (b >= 32) incl += warpTot[w - 1];
    g_blockOffsets[b * N_EXPERTS + e] = incl - v;
    if (b == 63) tot[e] = incl;
    __syncthreads();
    if (tid < N_EXPERTS) g_total[tid] = tot[tid];
    if (tid == 0) {
        float aux = 0.f; int drop = 0;
        for (int k = 0; k < N_EXPERTS; k++) {
            int tt = tot[k];
            int kept = tt < CAPACITY ? tt : CAPACITY;
            drop += tt - kept;
            float fi = (float)kept / (float)T_TOKENS;
            float pi = g_pi_sum[k] / (float)T_TOKENS;
            aux += fi * pi;
        }
        g_aux = aux * (float)N_EXPERTS;
        g_dropped = drop;
    }
}

__global__ void rank_kernel() {
    __shared__ int warpCnt[32][N_EXPERTS];
    __shared__ int warpOff[32][N_EXPERTS];
    int tid = threadIdx.x, w = tid >> 5, lane = tid & 31;
    int t = blockIdx.x * 1024 + tid;
    int e = g_expert[t];
    unsigned lt = (lane == 0) ? 0u : (0xffffffffu >> (32 - lane));
    int myrank = 0;
#pragma unroll
    for (int k = 0; k < N_EXPERTS; k++) {
        unsigned m = __ballot_sync(0xffffffffu, e == k);
        if (lane == 0) warpCnt[w][k] = __popc(m);
        if (e == k) myrank = __popc(m & lt);
    }
    __syncthreads();
    if (tid < 32 * N_EXPERTS) {
        int ww = tid >> 3, k = tid & 7;
        int s = 0;
        for (int u = 0; u < ww; u++) s += warpCnt[u][k];
        warpOff[ww][k] = s;
    }
    __syncthreads();
    int pos = g_blockOffsets[blockIdx.x * N_EXPERTS + e] + warpOff[w][e] + myrank;
    g_pos[t] = pos;
    if (pos < CAPACITY) g_slot2tok[e * CAPACITY + pos] = t;
}

// ---------------- fp16 mma.sync GEMM, BK=64, 4-stage ring ----------------
template<int K_TOT, bool GATHER, bool RELU>
__global__ void __launch_bounds__(512, 1)
gemm_mma(float* __restrict__ Dglob) {
    extern __shared__ __half smemh[];
    __half* sA = smemh;
    __half* sB = smemh + NSTAGE * STAGE_H;
    int* tokS = (int*)(smemh + 2 * NSTAGE * STAGE_H);

    int e = blockIdx.z;
    int ne = g_total[e]; if (ne > CAPACITY) ne = CAPACITY;
    int m0 = blockIdx.y * 128;
    if (m0 >= ne) return;
    int n0 = blockIdx.x * 128;

    int tid = threadIdx.x;
    int wid = tid >> 5, lane = tid & 31;
    int wm = wid >> 2, wn = wid & 3;
    int qr = lane >> 2, j = lane & 3;

    if (GATHER && tid < 128) {
        int m = m0 + tid;
        tokS[tid] = (m < ne) ? g_slot2tok[e * CAPACITY + m] : 0;
    }
    __syncthreads();

    const __half* Bbase = (RELU ? g_Wih : g_Woh) +
        ((size_t)e * (RELU ? D_FF : D_MODEL) + n0) * K_TOT;
    const __half* Hbase = g_Hh + ((size_t)e * CAPACITY + m0) * (size_t)D_FF;

    int lrow = tid >> 2, lq = tid & 3;
    const __half* aRowPtr;
    if (GATHER) aRowPtr = g_xh + (size_t)tokS[lrow] * D_MODEL + lq * 16;
    else        aRowPtr = Hbase + (size_t)lrow * D_FF + lq * 16;
    const __half* bRowPtr = Bbase + (size_t)lrow * K_TOT + lq * 16;
    uint32_t sAu = s2u(sA) + (lrow * LDS_H + lq * 16) * 2;
    uint32_t sBu = s2u(sB) + (lrow * LDS_H + lq * 16) * 2;

    float acc[2][4][4];
#pragma unroll
    for (int mi = 0; mi < 2; mi++)
#pragma unroll
        for (int ni = 0; ni < 4; ni++)
#pragma unroll
            for (int r = 0; r < 4; r++) acc[mi][ni][r] = 0.f;

    const int NS = K_TOT / BK;
    // prologue: stages 0..2 in flight
#pragma unroll
    for (int s = 0; s < 3; s++) {
        uint32_t so = s * STAGE_B2;
        cpasync16(sAu + so,      aRowPtr + s * BK);
        cpasync16(sAu + so + 16, aRowPtr + s * BK + 8);
        cpasync16(sBu + so,      bRowPtr + s * BK);
        cpasync16(sBu + so + 16, bRowPtr + s * BK + 8);
        asm volatile("cp.async.commit_group;" ::: "memory");
    }

    int cur = 0, pre = 3;
    for (int s = 0; s < NS; s++) {
        asm volatile("cp.async.wait_group 2;" ::: "memory");
        __syncthreads();
        if (s + 3 < NS) {
            uint32_t so = pre * STAGE_B2;
            const __half* ap = aRowPtr + (s + 3) * BK;
            const __half* bp = bRowPtr + (s + 3) * BK;
            cpasync16(sAu + so,      ap);
            cpasync16(sAu + so + 16, ap + 8);
            cpasync16(sBu + so,      bp);
            cpasync16(sBu + so + 16, bp + 8);
        }
        asm volatile("cp.async.commit_group;" ::: "memory");

        const __half* A = sA + cur * STAGE_H;
        const __half* B = sB + cur * STAGE_H;

#pragma unroll
        for (int kc = 0; kc < 4; kc++) {
            int co = kc * 16 + j * 4;
            uint2 af[2][2], bf[4];
#pragma unroll
            for (int mi = 0; mi < 2; mi++) {
                int r = wm * 32 + mi * 16 + qr;
                af[mi][0] = *(const uint2*)&A[r * LDS_H + co];
                af[mi][1] = *(const uint2*)&A[(r + 8) * LDS_H + co];
            }
#pragma unroll
            for (int ni = 0; ni < 4; ni++) {
                int r = wn * 32 + ni * 8 + qr;
                bf[ni] = *(const uint2*)&B[r * LDS_H + co];
            }
#pragma unroll
            for (int mi = 0; mi < 2; mi++)
#pragma unroll
                for (int ni = 0; ni < 4; ni++)
                    mma16(acc[mi][ni],
                          af[mi][0].x, af[mi][1].x, af[mi][0].y, af[mi][1].y,
                          bf[ni].x, bf[ni].y);
        }
        cur++; if (cur == NSTAGE) cur = 0;
        pre++; if (pre == NSTAGE) pre = 0;
    }

    // epilogue
#pragma unroll
    for (int mi = 0; mi < 2; mi++) {
#pragma unroll
        for (int half = 0; half < 2; half++) {
            int m = m0 + wm * 32 + mi * 16 + qr + half * 8;
            bool valid = m < ne;
            if (!valid) continue;
            if (RELU) {
                __half* rowptr = g_Hh + ((size_t)e * CAPACITY + m) * D_FF + n0;
#pragma unroll
                for (int ni = 0; ni < 4; ni++) {
                    float v0 = fmaxf(acc[mi][ni][half * 2 + 0], 0.f);
                    float v1 = fmaxf(acc[mi][ni][half * 2 + 1], 0.f);
                    int c = wn * 32 + ni * 8 + 2 * j;
                    int base16 = c & ~15;
                    int cm = c & 15;
                    int off = 4 * ((cm & 7) >> 1) + 2 * (cm >> 3);
                    __half2 hv = __floats2half2_rn(v0, v1);
                    *(__half2*)(rowptr + base16 + off) = hv;
                }
            } else {
                int tk = g_slot2tok[e * CAPACITY + m];
                float sc = g_top1[tk];
                float* rowptr = Dglob + (size_t)tk * D_MODEL + n0;
#pragma unroll
                for (int ni = 0; ni < 4; ni++) {
                    int c = wn * 32 + ni * 8 + 2 * j;
                    float2 v;
                    v.x = acc[mi][ni][half * 2 + 0] * sc;
                    v.y = acc[mi][ni][half * 2 + 1] * sc;
                    *(float2*)(rowptr + c) = v;
                }
            }
        }
    }
}

__global__ void drop_kernel(float* __restrict__ outp) {
    for (int t = blockIdx.x * blockDim.x + threadIdx.x; t < T_TOKENS;
         t += gridDim.x * blockDim.x) {
        if (g_pos[t] >= CAPACITY) {
            float4 z = make_float4(0.f, 0.f, 0.f, 0.f);
            float4* p = (float4*)(outp + (size_t)t * D_MODEL);
            for (int i = 0; i < D_MODEL / 4; i++) p[i] = z;
        }
    }
}

__global__ void extras_kernel(float* __restrict__ outp, long long out_size) {
    long long i = (long long)blockIdx.x * blockDim.x + threadIdx.x;
    long long off = OUT_ELEMS + i;
    if (off >= out_size) return;
    long long r = i;
    if (r < ONEHOT_E) {
        int t = (int)(r >> 3), e = (int)(r & 7);
        outp[off] = (g_expert[t] == e && g_pos[t] < CAPACITY) ? 1.f : 0.f;
        return;
    }
    r -= ONEHOT_E;
    if (r < T_TOKENS) { outp[off] = g_top1[r]; return; }
    r -= T_TOKENS;
    if (r < PROBS_E) { outp[off] = g_probs[r]; return; }
    r -= PROBS_E;
    if (r == 0) { outp[off] = g_aux; return; }
    outp[off] = (float)g_dropped;
}

// ---------------- launch ----------------
extern "C" void kernel_launch(void* const* d_in, const int* in_sizes, int n_in,
                              void* d_out, int out_size) {
    const float* x  = (const float*)d_in[0];
    const float* Wr = (const float*)d_in[1];
    const float* br = (const float*)d_in[2];
    const float* Wi = (const float*)d_in[3];
    const float* Wo = (const float*)d_in[4];
    float* outp = (float*)d_out;

    cudaFuncSetAttribute(gemm_mma<D_MODEL, true, true>,
                         cudaFuncAttributeMaxDynamicSharedMemorySize, SMEM_GEMM);
    cudaFuncSetAttribute(gemm_mma<D_FF, false, false>,
                         cudaFuncAttributeMaxDynamicSharedMemorySize, SMEM_GEMM);

    zero_kernel<<<1, 32>>>();
    router_kernel<<<T_TOKENS / 8, 256>>>(x, Wr, br);
    count_kernel<<<NB, 1024>>>();
    scan_kernel<<<1, 512>>>();
    rank_kernel<<<NB, 1024>>>();

    cvt_perm_kernel<1><<<(unsigned)(((long long)N_EXPERTS * D_FF * D_MODEL / 16) / 256), 256>>>(Wi);
    cvt_perm_kernel<2><<<(unsigned)(((long long)N_EXPERTS * D_MODEL * D_FF / 16) / 256), 256>>>(Wo);

    dim3 g1(D_FF / 128, CAPACITY / 128, N_EXPERTS);
    gemm_mma<D_MODEL, true, true><<<g1, 512, SMEM_GEMM>>>(nullptr);
    dim3 g2(D_MODEL / 128, CAPACITY / 128, N_EXPERTS);
    gemm_mma<D_FF, false, false><<<g2, 512, SMEM_GEMM>>>(outp);

    drop_kernel<<<256, 256>>>(outp);

    long long extra = (long long)out_size - OUT_ELEMS;
    if (extra > 0) {
        unsigned nb = (unsigned)((extra + 255) / 256);
        extras_kernel<<<nb, 256>>>(outp, (long long)out_size);
    }
}

// round 11
// speedup vs baseline: 4.7376x; 1.0573x over previous
#include <cuda_runtime.h>
#include <cuda_fp16.h>
#include <math.h>
#include <stdint.h>

#define D_MODEL   512
#define D_FF      2048
#define N_EXPERTS 8
#define CAPACITY  10240
#define T_TOKENS  65536
#define NB        64

#define OUT_ELEMS   ((long long)T_TOKENS * D_MODEL)
#define ONEHOT_E    ((long long)T_TOKENS * N_EXPERTS)
#define PROBS_E     ((long long)T_TOKENS * N_EXPERTS)

// fp16 GEMM smem: 3-stage ring, block tile 128(M) x 256(N), BK=64.
// A stage: 128 rows x 80 halves; B stage: 256 rows x 80 halves.
#define BK        64
#define LDS_H     80
#define STAGE_A_H (128 * LDS_H)          // 10240 halves
#define STAGE_B_H (256 * LDS_H)          // 20480 halves
#define NSTAGE    3
#define SMEM_GEMM ((NSTAGE * (STAGE_A_H + STAGE_B_H)) * 2 + 512 + 128)  // ~185 KB

// ---------------- scratch ----------------
__device__ float g_probs[T_TOKENS * N_EXPERTS];
__device__ float g_top1[T_TOKENS];
__device__ int   g_expert[T_TOKENS];
__device__ int   g_pos[T_TOKENS];
__device__ int   g_blockCounts[NB * N_EXPERTS];
__device__ int   g_blockOffsets[NB * N_EXPERTS];
__device__ int   g_total[N_EXPERTS];
__device__ float g_pi_sum[N_EXPERTS];
__device__ float g_aux;
__device__ int   g_dropped;
__device__ int   g_slot2tok[N_EXPERTS * CAPACITY];
// fp16, k-permuted within 16-groups: p(k) = 4*((k&7)>>1) + (k&1) + 2*(k>>3)
__device__ __half g_xh[(size_t)T_TOKENS * D_MODEL];
__device__ __half g_Wih[(size_t)N_EXPERTS * D_FF * D_MODEL];
__device__ __half g_Woh[(size_t)N_EXPERTS * D_MODEL * D_FF];
__device__ __half g_Hh[(size_t)N_EXPERTS * CAPACITY * D_FF];

// ---------------- helpers ----------------
__device__ __forceinline__ uint32_t s2u(const void* p) {
    uint32_t a;
    asm("{ .reg .u64 t; cvta.to.shared.u64 t, %1; cvt.u32.u64 %0, t; }" : "=r"(a) : "l"(p));
    return a;
}
__device__ __forceinline__ void cpasync16(uint32_t saddr, const void* gaddr) {
    asm volatile("cp.async.cg.shared.global [%0], [%1], 16;" :: "r"(saddr), "l"(gaddr) : "memory");
}
__device__ __forceinline__ void mma16(float* c, uint32_t a0, uint32_t a1, uint32_t a2,
                                      uint32_t a3, uint32_t b0, uint32_t b1) {
    asm volatile(
        "mma.sync.aligned.m16n8k16.row.col.f32.f16.f16.f32 "
        "{%0,%1,%2,%3}, {%4,%5,%6,%7}, {%8,%9}, {%0,%1,%2,%3};"
        : "+f"(c[0]), "+f"(c[1]), "+f"(c[2]), "+f"(c[3])
        : "r"(a0), "r"(a1), "r"(a2), "r"(a3), "r"(b0), "r"(b1));
}
__device__ __forceinline__ int permk16(int k) {
    return 4 * ((k & 7) >> 1) + (k & 1) + 2 * (k >> 3);
}

// ---------------- weight cvt+permute to fp16 (once per call) ----------------
template<int WHICH>
__global__ void cvt_perm_kernel(const float* __restrict__ s) {
    long long g = (long long)blockIdx.x * 256 + threadIdx.x;
    long long base = g * 16;
    __half out[16];
#pragma unroll
    for (int q = 0; q < 4; q++) {
        float4 v = *(const float4*)(s + base + q * 4);
        float vals[4] = {v.x, v.y, v.z, v.w};
#pragma unroll
        for (int u = 0; u < 4; u++) {
            int k = q * 4 + u;
            out[permk16(k)] = __float2half_rn(vals[u]);
        }
    }
    __half* dst = (WHICH == 1) ? g_Wih : g_Woh;
    *(uint4*)(dst + base) = *(uint4*)out;
    *(uint4*)(dst + base + 8) = *(uint4*)(out + 8);
}

// ---------------- routing ----------------
__global__ void zero_kernel() {
    int i = threadIdx.x;
    if (i < N_EXPERTS) g_pi_sum[i] = 0.f;
}

// One warp per token; fused: router + x->fp16 permuted conversion (L1-hot).
__global__ void router_kernel(const float* __restrict__ x,
                              const float* __restrict__ Wr,
                              const float* __restrict__ br) {
    __shared__ float Ws[N_EXPERTS * D_MODEL];
    __shared__ float brs[N_EXPERTS];
    __shared__ float pis[N_EXPERTS];
    int tid = threadIdx.x;
    for (int i = tid; i < N_EXPERTS * D_MODEL; i += 256) Ws[i] = Wr[i];
    if (tid < N_EXPERTS) { brs[tid] = br[tid]; pis[tid] = 0.f; }
    __syncthreads();

    int warp = tid >> 5, lane = tid & 31;
    int t = blockIdx.x * 8 + warp;

    float acc[N_EXPERTS];
#pragma unroll
    for (int e = 0; e < N_EXPERTS; e++) acc[e] = 0.f;
    const float* xr = x + (size_t)t * D_MODEL;
#pragma unroll
    for (int i = 0; i < D_MODEL / 32; i++) {
        int c = lane + i * 32;
        float v = xr[c];
#pragma unroll
        for (int e = 0; e < N_EXPERTS; e++) acc[e] += v * Ws[e * D_MODEL + c];
    }

    // fused fp16 convert + k16-permute
    {
        __half out[16];
        const float4* xq = (const float4*)xr + lane * 4;
#pragma unroll
        for (int q = 0; q < 4; q++) {
            float4 v = xq[q];
            float vals[4] = {v.x, v.y, v.z, v.w};
#pragma unroll
            for (int u = 0; u < 4; u++) {
                int k = q * 4 + u;
                out[permk16(k)] = __float2half_rn(vals[u]);
            }
        }
        uint4* dst = (uint4*)(g_xh + (size_t)t * D_MODEL + lane * 16);
        dst[0] = *(uint4*)out;
        dst[1] = *(uint4*)(out + 8);
    }

#pragma unroll
    for (int e = 0; e < N_EXPERTS; e++) {
#pragma unroll
        for (int off = 16; off > 0; off >>= 1)
            acc[e] += __shfl_down_sync(0xffffffffu, acc[e], off);
    }
    if (lane == 0) {
        float l[N_EXPERTS];
        float mx = -INFINITY; int idx = 0;
#pragma unroll
        for (int e = 0; e < N_EXPERTS; e++) {
            l[e] = acc[e] + brs[e];
            if (l[e] > mx) { mx = l[e]; idx = e; }
        }
        float s = 0.f, pr[N_EXPERTS];
#pragma unroll
        for (int e = 0; e < N_EXPERTS; e++) { pr[e] = expf(l[e] - mx); s += pr[e]; }
        float inv = 1.f / s;
#pragma unroll
        for (int e = 0; e < N_EXPERTS; e++) {
            float p = pr[e] * inv;
            g_probs[(size_t)t * N_EXPERTS + e] = p;
            atomicAdd(&pis[e], p);
        }
        g_top1[t] = pr[idx] * inv;
        g_expert[t] = idx;
    }
    __syncthreads();
    if (tid < N_EXPERTS) atomicAdd(&g_pi_sum[tid], pis[tid]);
}

__global__ void count_kernel() {
    __shared__ int c[N_EXPERTS];
    if (threadIdx.x < N_EXPERTS) c[threadIdx.x] = 0;
    __syncthreads();
    int t = blockIdx.x * 1024 + threadIdx.x;
    atomicAdd(&c[g_expert[t]], 1);
    __syncthreads();
    if (threadIdx.x < N_EXPERTS)
        g_blockCounts[blockIdx.x * N_EXPERTS + threadIdx.x] = c[threadIdx.x];
}

// Parallel scan: 512 threads; tid = e*64 + b.
__global__ void scan_kernel() {
    __shared__ int warpTot[16];
    __shared__ int tot[N_EXPERTS];
    int tid = threadIdx.x;
    int e = tid >> 6, b = tid & 63;
    int w = tid >> 5, lane = tid & 31;
    int v = g_blockCounts[b * N_EXPERTS + e];
    int incl = v;
#pragma unroll
    for (int off = 1; off < 32; off <<= 1) {
        int n = __shfl_up_sync(0xffffffffu, incl, off);
        if (lane >= off) incl += n;
    }
    if (lane == 31) warpTot[w] = incl;
    __syncthreads();
    if (b >= 32) incl += warpTot[w - 1];
    g_blockOffsets[b * N_EXPERTS + e] = incl - v;
    if (b == 63) tot[e] = incl;
    __syncthreads();
    if (tid < N_EXPERTS) g_total[tid] = tot[tid];
    if (tid == 0) {
        float aux = 0.f; int drop = 0;
        for (int k = 0; k < N_EXPERTS; k++) {
            int tt = tot[k];
            int kept = tt < CAPACITY ? tt : CAPACITY;
            drop += tt - kept;
            float fi = (float)kept / (float)T_TOKENS;
            float pi = g_pi_sum[k] / (float)T_TOKENS;
            aux += fi * pi;
        }
        g_aux = aux * (float)N_EXPERTS;
        g_dropped = drop;
    }
}

__global__ void rank_kernel() {
    __shared__ int warpCnt[32][N_EXPERTS];
    __shared__ int warpOff[32][N_EXPERTS];
    int tid = threadIdx.x, w = tid >> 5, lane = tid & 31;
    int t = blockIdx.x * 1024 + tid;
    int e = g_expert[t];
    unsigned lt = (lane == 0) ? 0u : (0xffffffffu >> (32 - lane));
    int myrank = 0;
#pragma unroll
    for (int k = 0; k < N_EXPERTS; k++) {
        unsigned m = __ballot_sync(0xffffffffu, e == k);
        if (lane == 0) warpCnt[w][k] = __popc(m);
        if (e == k) myrank = __popc(m & lt);
    }
    __syncthreads();
    if (tid < 32 * N_EXPERTS) {
        int ww = tid >> 3, k = tid & 7;
        int s = 0;
        for (int u = 0; u < ww; u++) s += warpCnt[u][k];
        warpOff[ww][k] = s;
    }
    __syncthreads();
    int pos = g_blockOffsets[blockIdx.x * N_EXPERTS + e] + warpOff[w][e] + myrank;
    g_pos[t] = pos;
    if (pos < CAPACITY) g_slot2tok[e * CAPACITY + pos] = t;
}

// ---------------- fp16 mma.sync GEMM, 128x256 tile, BK=64, 3-stage ----------------
// warp tile 32(M) x 64(N); 4x4 warps.
template<int K_TOT, bool GATHER, bool RELU>
__global__ void __launch_bounds__(512, 1)
gemm_mma(float* __restrict__ Dglob) {
    extern __shared__ __half smemh[];
    __half* sA = smemh;                                  // 3 x 128x80
    __half* sB = smemh + NSTAGE * STAGE_A_H;             // 3 x 256x80
    int* tokS = (int*)(smemh + NSTAGE * (STAGE_A_H + STAGE_B_H));

    int e = blockIdx.z;
    int ne = g_total[e]; if (ne > CAPACITY) ne = CAPACITY;
    int m0 = blockIdx.y * 128;
    if (m0 >= ne) return;
    int n0 = blockIdx.x * 256;

    int tid = threadIdx.x;
    int wid = tid >> 5, lane = tid & 31;
    int wm = wid >> 2, wn = wid & 3;
    int qr = lane >> 2, j = lane & 3;

    if (GATHER && tid < 128) {
        int m = m0 + tid;
        tokS[tid] = (m < ne) ? g_slot2tok[e * CAPACITY + m] : 0;
    }
    __syncthreads();

    const __half* Bbase = (RELU ? g_Wih : g_Woh) +
        ((size_t)e * (RELU ? D_FF : D_MODEL) + n0) * K_TOT;
    const __half* Hbase = g_Hh + ((size_t)e * CAPACITY + m0) * (size_t)D_FF;

    // A loader: 4 threads/row, 16 halves (2 x cp16) each
    int lrowA = tid >> 2, lqA = tid & 3;
    const __half* aRowPtr;
    if (GATHER) aRowPtr = g_xh + (size_t)tokS[lrowA] * D_MODEL + lqA * 16;
    else        aRowPtr = Hbase + (size_t)lrowA * D_FF + lqA * 16;
    uint32_t sAu = s2u(sA) + (lrowA * LDS_H + lqA * 16) * 2;
    // B loader: 2 threads/row, 32 halves (4 x cp16) each
    int lrowB = tid >> 1, lqB = tid & 1;
    const __half* bRowPtr = Bbase + (size_t)lrowB * K_TOT + lqB * 32;
    uint32_t sBu = s2u(sB) + (lrowB * LDS_H + lqB * 32) * 2;

    float acc[2][8][4];
#pragma unroll
    for (int mi = 0; mi < 2; mi++)
#pragma unroll
        for (int ni = 0; ni < 8; ni++)
#pragma unroll
            for (int r = 0; r < 4; r++) acc[mi][ni][r] = 0.f;

    const int NS = K_TOT / BK;
    // prologue: 2 stages in flight
#pragma unroll
    for (int s = 0; s < 2; s++) {
        uint32_t soA = s * STAGE_A_H * 2;
        uint32_t soB = s * STAGE_B_H * 2;
        const __half* ap = aRowPtr + s * BK;
        const __half* bp = bRowPtr + s * BK;
        cpasync16(sAu + soA,      ap);
        cpasync16(sAu + soA + 16, ap + 8);
        cpasync16(sBu + soB,      bp);
        cpasync16(sBu + soB + 16, bp + 8);
        cpasync16(sBu + soB + 32, bp + 16);
        cpasync16(sBu + soB + 48, bp + 24);
        asm volatile("cp.async.commit_group;" ::: "memory");
    }

    int cur = 0, pre = 2;
    for (int s = 0; s < NS; s++) {
        asm volatile("cp.async.wait_group 1;" ::: "memory");
        __syncthreads();
        if (s + 2 < NS) {
            uint32_t soA = pre * STAGE_A_H * 2;
            uint32_t soB = pre * STAGE_B_H * 2;
            const __half* ap = aRowPtr + (s + 2) * BK;
            const __half* bp = bRowPtr + (s + 2) * BK;
            cpasync16(sAu + soA,      ap);
            cpasync16(sAu + soA + 16, ap + 8);
            cpasync16(sBu + soB,      bp);
            cpasync16(sBu + soB + 16, bp + 8);
            cpasync16(sBu + soB + 32, bp + 16);
            cpasync16(sBu + soB + 48, bp + 24);
        }
        asm volatile("cp.async.commit_group;" ::: "memory");

        const __half* A = sA + cur * STAGE_A_H;
        const __half* B = sB + cur * STAGE_B_H;

#pragma unroll
        for (int kc = 0; kc < 4; kc++) {
            int co = kc * 16 + j * 4;
            uint2 af[2][2], bf[8];
#pragma unroll
            for (int mi = 0; mi < 2; mi++) {
                int r = wm * 32 + mi * 16 + qr;
                af[mi][0] = *(const uint2*)&A[r * LDS_H + co];
                af[mi][1] = *(const uint2*)&A[(r + 8) * LDS_H + co];
            }
#pragma unroll
            for (int ni = 0; ni < 8; ni++) {
                int r = wn * 64 + ni * 8 + qr;
                bf[ni] = *(const uint2*)&B[r * LDS_H + co];
            }
#pragma unroll
            for (int mi = 0; mi < 2; mi++)
#pragma unroll
                for (int ni = 0; ni < 8; ni++)
                    mma16(acc[mi][ni],
                          af[mi][0].x, af[mi][1].x, af[mi][0].y, af[mi][1].y,
                          bf[ni].x, bf[ni].y);
        }
        cur++; if (cur == NSTAGE) cur = 0;
        pre++; if (pre == NSTAGE) pre = 0;
    }

    // epilogue
#pragma unroll
    for (int mi = 0; mi < 2; mi++) {
#pragma unroll
        for (int half = 0; half < 2; half++) {
            int m = m0 + wm * 32 + mi * 16 + qr + half * 8;
            if (m >= ne) continue;
            if (RELU) {
                __half* rowptr = g_Hh + ((size_t)e * CAPACITY + m) * D_FF + n0;
#pragma unroll
                for (int ni = 0; ni < 8; ni++) {
                    float v0 = fmaxf(acc[mi][ni][half * 2 + 0], 0.f);
                    float v1 = fmaxf(acc[mi][ni][half * 2 + 1], 0.f);
                    int c = wn * 64 + ni * 8 + 2 * j;
                    int base16 = c & ~15;
                    int cm = c & 15;
                    int off = 4 * ((cm & 7) >> 1) + 2 * (cm >> 3);
                    __half2 hv = __floats2half2_rn(v0, v1);
                    *(__half2*)(rowptr + base16 + off) = hv;
                }
            } else {
                int tk = g_slot2tok[e * CAPACITY + m];
                float sc = g_top1[tk];
                float* rowptr = Dglob + (size_t)tk * D_MODEL + n0;
#pragma unroll
                for (int ni = 0; ni < 8; ni++) {
                    int c = wn * 64 + ni * 8 + 2 * j;
                    float2 v;
                    v.x = acc[mi][ni][half * 2 + 0] * sc;
                    v.y = acc[mi][ni][half * 2 + 1] * sc;
                    *(float2*)(rowptr + c) = v;
                }
            }
        }
    }
}

__global__ void drop_kernel(float* __restrict__ outp) {
    for (int t = blockIdx.x * blockDim.x + threadIdx.x; t < T_TOKENS;
         t += gridDim.x * blockDim.x) {
        if (g_pos[t] >= CAPACITY) {
            float4 z = make_float4(0.f, 0.f, 0.f, 0.f);
            float4* p = (float4*)(outp + (size_t)t * D_MODEL);
            for (int i = 0; i < D_MODEL / 4; i++) p[i] = z;
        }
    }
}

__global__ void extras_kernel(float* __restrict__ outp, long long out_size) {
    long long i = (long long)blockIdx.x * blockDim.x + threadIdx.x;
    long long off = OUT_ELEMS + i;
    if (off >= out_size) return;
    long long r = i;
    if (r < ONEHOT_E) {
        int t = (int)(r >> 3), e = (int)(r & 7);
        outp[off] = (g_expert[t] == e && g_pos[t] < CAPACITY) ? 1.f : 0.f;
        return;
    }
    r -= ONEHOT_E;
    if (r < T_TOKENS) { outp[off] = g_top1[r]; return; }
    r -= T_TOKENS;
    if (r < PROBS_E) { outp[off] = g_probs[r]; return; }
    r -= PROBS_E;
    if (r == 0) { outp[off] = g_aux; return; }
    outp[off] = (float)g_dropped;
}

// ---------------- launch ----------------
extern "C" void kernel_launch(void* const* d_in, const int* in_sizes, int n_in,
                              void* d_out, int out_size) {
    const float* x  = (const float*)d_in[0];
    const float* Wr = (const float*)d_in[1];
    const float* br = (const float*)d_in[2];
    const float* Wi = (const float*)d_in[3];
    const float* Wo = (const float*)d_in[4];
    float* outp = (float*)d_out;

    cudaFuncSetAttribute(gemm_mma<D_MODEL, true, true>,
                         cudaFuncAttributeMaxDynamicSharedMemorySize, SMEM_GEMM);
    cudaFuncSetAttribute(gemm_mma<D_FF, false, false>,
                         cudaFuncAttributeMaxDynamicSharedMemorySize, SMEM_GEMM);

    zero_kernel<<<1, 32>>>();
    router_kernel<<<T_TOKENS / 8, 256>>>(x, Wr, br);
    count_kernel<<<NB, 1024>>>();
    scan_kernel<<<1, 512>>>();
    rank_kernel<<<NB, 1024>>>();

    cvt_perm_kernel<1><<<(unsigned)(((long long)N_EXPERTS * D_FF * D_MODEL / 16) / 256), 256>>>(Wi);
    cvt_perm_kernel<2><<<(unsigned)(((long long)N_EXPERTS * D_MODEL * D_FF / 16) / 256), 256>>>(Wo);

    dim3 g1(D_FF / 256, CAPACITY / 128, N_EXPERTS);
    gemm_mma<D_MODEL, true, true><<<g1, 512, SMEM_GEMM>>>(nullptr);
    dim3 g2(D_MODEL / 256, CAPACITY / 128, N_EXPERTS);
    gemm_mma<D_FF, false, false><<<g2, 512, SMEM_GEMM>>>(outp);

    drop_kernel<<<256, 256>>>(outp);

    long long extra = (long long)out_size - OUT_ELEMS;
    if (extra > 0) {
        unsigned nb = (unsigned)((extra + 255) / 256);
        extras_kernel<<<nb, 256>>>(outp, (long long)out_size);
    }
}